// round 2
// baseline (speedup 1.0000x reference)
#include <cuda_runtime.h>
#include <math.h>

#define BSZ   4
#define SEQ   1024
#define DIM   768
#define NH    12
#define HD    64
#define ROWS  (BSZ*SEQ)      // 4096
#define NBH   (BSZ*NH)       // 48
#define NITER 2

// ---------------- static scratch (no allocations allowed) ----------------
__device__ float g_im [ROWS*DIM];
__device__ float g_q  [ROWS*DIM];
__device__ float g_k  [ROWS*DIM];
__device__ float g_v  [ROWS*DIM];
__device__ float g_sa [ROWS*DIM];
__device__ float g_z  [ROWS*DIM];
__device__ float g_t1 [ROWS*DIM];
__device__ float g_v2 [ROWS*DIM];
__device__ float g_av2[ROWS*DIM];
__device__ float g_m2 [ROWS*DIM];
__device__ float g_t2 [ROWS*DIM];
__device__ float g_ff [ROWS*DIM];
__device__ float g_q2 [ROWS*DIM];
__device__ float g_k2 [ROWS*DIM];
__device__ float g_S  [(size_t)NBH*SEQ*SEQ];   // self-attn scores (reused per layer)
__device__ float g_A2 [(size_t)NBH*SEQ*SEQ];   // cross-attn probs (computed ONCE)
__device__ double g_sum [DIM];
__device__ double g_sum2[DIM];
__device__ float  g_bnsc[DIM];
__device__ float  g_bnsh[DIM];

// ---------------- embedding + positional encoding ----------------
// out = 2*embed[x] + pos   (forward does embed + (embed+pos))
__global__ void embed_pos_kernel(const int* __restrict__ x,
                                 const float* __restrict__ embed,
                                 float* __restrict__ out)
{
    int idx = blockIdx.x * 256 + threadIdx.x;
    if (idx >= ROWS*DIM) return;
    int r = idx / DIM, d = idx - r*DIM;
    int s = r & (SEQ-1);
    int tok = x[r];
    int i = d >> 1;
    float inv = powf(10000.0f, -2.0f * (float)i / (float)DIM);
    float ang = (float)s * inv;
    float pe = (d & 1) ? cosf(ang) : sinf(ang);
    out[idx] = 2.0f * embed[(size_t)tok * DIM + d] + pe;
}

// ---------------- generic GEMM: C[M,N] = A[:, aoff:aoff+K] @ W[K,N] + bias ----------------
// 64x64 tile, BK=16, 256 threads, 4x4 per thread.
__global__ __launch_bounds__(256)
void gemm_bias(const float* __restrict__ A, int lda, int aoff,
               const float* __restrict__ W,
               const float* __restrict__ bias,
               float* __restrict__ C,
               int N, int K, int relu)
{
    __shared__ float As[16][64];
    __shared__ float Bs[16][64];
    int tid = threadIdx.x;
    int tx = tid & 15, ty = tid >> 4;
    int bm = blockIdx.y * 64, bn = blockIdx.x * 64;
    const float* Ab = A + (size_t)bm * lda + aoff;

    float c[4][4];
#pragma unroll
    for (int i=0;i<4;i++)
#pragma unroll
        for (int j=0;j<4;j++) c[i][j]=0.f;

    int lm = tid >> 2, lq = tid & 3;        // A-tile loader coords
    int lk = tid >> 4, ln = tid & 15;       // B-tile loader coords

    for (int kb = 0; kb < K; kb += 16) {
        float4 va = *reinterpret_cast<const float4*>(Ab + (size_t)lm*lda + kb + 4*lq);
        As[4*lq+0][lm]=va.x; As[4*lq+1][lm]=va.y; As[4*lq+2][lm]=va.z; As[4*lq+3][lm]=va.w;
        float4 vb = *reinterpret_cast<const float4*>(W + (size_t)(kb+lk)*N + bn + 4*ln);
        *reinterpret_cast<float4*>(&Bs[lk][4*ln]) = vb;
        __syncthreads();
#pragma unroll
        for (int k = 0; k < 16; k++) {
            float4 a4 = *reinterpret_cast<const float4*>(&As[k][ty*4]);
            float4 b4 = *reinterpret_cast<const float4*>(&Bs[k][tx*4]);
            float a[4] = {a4.x,a4.y,a4.z,a4.w};
            float b[4] = {b4.x,b4.y,b4.z,b4.w};
#pragma unroll
            for (int i=0;i<4;i++)
#pragma unroll
                for (int j=0;j<4;j++) c[i][j] = fmaf(a[i], b[j], c[i][j]);
        }
        __syncthreads();
    }
#pragma unroll
    for (int i=0;i<4;i++) {
        int m = bm + ty*4 + i;
#pragma unroll
        for (int j=0;j<4;j++) {
            int n = bn + tx*4 + j;
            float v = c[i][j] + bias[n];
            if (relu) v = fmaxf(v, 0.f);
            C[(size_t)m*N + n] = v;
        }
    }
}

// ---------------- batched attention scores: S[bh,q,t] = scale * sum_e Q[bh,q,e]*K[bh,t,e] ----------------
// Q,K stored as [ROWS, DIM] with head layout col = h*64+e. Grid (S/64, S/64, NBH).
__global__ __launch_bounds__(256)
void attn_scores(const float* __restrict__ Q, const float* __restrict__ K,
                 float* __restrict__ S, float scale)
{
    __shared__ float Qs[64][65];
    __shared__ float Ks[64][65];
    int bh = blockIdx.z;
    int b = bh / NH, h = bh - b*NH;
    int tid = threadIdx.x, tx = tid & 15, ty = tid >> 4;
    size_t base = ((size_t)b*SEQ)*DIM + h*HD;
    int q0 = blockIdx.y*64, t0 = blockIdx.x*64;

    // Full 64x64 tiles: 1024 float4s each, 4 iterations x 256 threads.
#pragma unroll
    for (int it = 0; it < 4; it++) {
        int idx = it*256 + tid;          // float4 slot id: 0..1023
        int r  = idx >> 4;               // 0..63
        int c4 = (idx & 15) * 4;         // 0,4,...,60
        float4 vq = *reinterpret_cast<const float4*>(&Q[base + (size_t)(q0+r)*DIM + c4]);
        Qs[r][c4+0]=vq.x; Qs[r][c4+1]=vq.y; Qs[r][c4+2]=vq.z; Qs[r][c4+3]=vq.w;
        float4 vk = *reinterpret_cast<const float4*>(&K[base + (size_t)(t0+r)*DIM + c4]);
        Ks[r][c4+0]=vk.x; Ks[r][c4+1]=vk.y; Ks[r][c4+2]=vk.z; Ks[r][c4+3]=vk.w;
    }
    __syncthreads();

    float c[4][4];
#pragma unroll
    for (int i=0;i<4;i++)
#pragma unroll
        for (int j=0;j<4;j++) c[i][j]=0.f;

#pragma unroll 8
    for (int k = 0; k < 64; k++) {
        float a[4], bb[4];
#pragma unroll
        for (int i=0;i<4;i++) a[i]  = Qs[ty*4+i][k];
#pragma unroll
        for (int j=0;j<4;j++) bb[j] = Ks[tx*4+j][k];
#pragma unroll
        for (int i=0;i<4;i++)
#pragma unroll
            for (int j=0;j<4;j++) c[i][j] = fmaf(a[i], bb[j], c[i][j]);
    }

    float* Sp = S + (size_t)bh*SEQ*SEQ;
#pragma unroll
    for (int i=0;i<4;i++)
#pragma unroll
        for (int j=0;j<4;j++)
            Sp[(size_t)(q0+ty*4+i)*SEQ + t0+tx*4+j] = c[i][j] * scale;
}

// ---------------- row softmax over last dim (SEQ) ----------------
__global__ __launch_bounds__(256)
void softmax_rows(float* __restrict__ S)
{
    float* row = S + (size_t)blockIdx.x * SEQ;
    __shared__ float red[256];
    int t = threadIdx.x;
    float m = -1e30f;
    for (int i = t; i < SEQ; i += 256) m = fmaxf(m, row[i]);
    red[t] = m; __syncthreads();
    for (int o = 128; o > 0; o >>= 1) { if (t < o) red[t] = fmaxf(red[t], red[t+o]); __syncthreads(); }
    m = red[0]; __syncthreads();
    float s = 0.f;
    for (int i = t; i < SEQ; i += 256) { float e = expf(row[i]-m); row[i] = e; s += e; }
    red[t] = s; __syncthreads();
    for (int o = 128; o > 0; o >>= 1) { if (t < o) red[t] += red[t+o]; __syncthreads(); }
    float inv = 1.0f / red[0];
    for (int i = t; i < SEQ; i += 256) row[i] *= inv;
}

// ---------------- batched A @ V: out[bh,q,e] (merged layout) ----------------
// Grid (S/64, 1, NBH). Output tile 64 rows x 64 (=HD) cols, K loop over SEQ in 16s.
__global__ __launch_bounds__(256)
void attn_av(const float* __restrict__ A, const float* __restrict__ V,
             float* __restrict__ O)
{
    __shared__ float As[64][17];
    __shared__ float Vs[16][65];
    int bh = blockIdx.z;
    int b = bh / NH, h = bh - b*NH;
    int tid = threadIdx.x, tx = tid & 15, ty = tid >> 4;
    int s0 = blockIdx.x * 64;
    const float* Ap = A + (size_t)bh*SEQ*SEQ;
    size_t vbase = ((size_t)b*SEQ)*DIM + h*HD;

    float c[4][4];
#pragma unroll
    for (int i=0;i<4;i++)
#pragma unroll
        for (int j=0;j<4;j++) c[i][j]=0.f;

    int ar = tid >> 2, aq = tid & 3;        // A loader: 1 float4/thread (64x16)
    int vk = tid >> 4, vq = tid & 15;       // V loader: 1 float4/thread (16x64)

    for (int t0 = 0; t0 < SEQ; t0 += 16) {
        float4 va = *reinterpret_cast<const float4*>(Ap + (size_t)(s0+ar)*SEQ + t0 + 4*aq);
        As[ar][4*aq+0]=va.x; As[ar][4*aq+1]=va.y; As[ar][4*aq+2]=va.z; As[ar][4*aq+3]=va.w;
        float4 vv = *reinterpret_cast<const float4*>(V + vbase + (size_t)(t0+vk)*DIM + 4*vq);
        Vs[vk][4*vq+0]=vv.x; Vs[vk][4*vq+1]=vv.y; Vs[vk][4*vq+2]=vv.z; Vs[vk][4*vq+3]=vv.w;
        __syncthreads();
#pragma unroll
        for (int k = 0; k < 16; k++) {
            float a[4], bb[4];
#pragma unroll
            for (int i=0;i<4;i++) a[i]  = As[ty*4+i][k];
#pragma unroll
            for (int j=0;j<4;j++) bb[j] = Vs[k][tx*4+j];
#pragma unroll
            for (int i=0;i<4;i++)
#pragma unroll
                for (int j=0;j<4;j++) c[i][j] = fmaf(a[i], bb[j], c[i][j]);
        }
        __syncthreads();
    }
#pragma unroll
    for (int i=0;i<4;i++) {
        size_t orow = ((size_t)b*SEQ + s0 + ty*4 + i)*DIM + h*HD;
#pragma unroll
        for (int j=0;j<4;j++)
            O[orow + tx*4 + j] = c[i][j];
    }
}

// ---------------- batch norm (training stats over all 4096 rows, per feature) ----------------
__global__ void bn_zero()
{
    int t = blockIdx.x*256 + threadIdx.x;
    if (t < DIM) { g_sum[t] = 0.0; g_sum2[t] = 0.0; }
}

// z = x + y; accumulate double sums per feature. Grid (24, 8), block (32, 8).
__global__ __launch_bounds__(256)
void bn_add_stats(const float* __restrict__ X, const float* __restrict__ Y,
                  float* __restrict__ Z)
{
    int f  = blockIdx.x*32 + threadIdx.x;
    int rb = blockIdx.y*512;
    double s = 0.0, s2 = 0.0;
    for (int r = rb + threadIdx.y; r < rb + 512; r += 8) {
        size_t idx = (size_t)r*DIM + f;
        float v = X[idx] + Y[idx];
        Z[idx] = v;
        s += v; s2 += (double)v * (double)v;
    }
    __shared__ double sh[2][8][32];
    sh[0][threadIdx.y][threadIdx.x] = s;
    sh[1][threadIdx.y][threadIdx.x] = s2;
    __syncthreads();
    if (threadIdx.y == 0) {
        double ts = 0.0, ts2 = 0.0;
#pragma unroll
        for (int i = 0; i < 8; i++) { ts += sh[0][i][threadIdx.x]; ts2 += sh[1][i][threadIdx.x]; }
        atomicAdd(&g_sum[f], ts);
        atomicAdd(&g_sum2[f], ts2);
    }
}

__global__ void bn_finalize(const float* __restrict__ g, const float* __restrict__ b)
{
    int f = blockIdx.x*256 + threadIdx.x;
    if (f >= DIM) return;
    double mu  = g_sum[f]  * (1.0 / ROWS);
    double var = g_sum2[f] * (1.0 / ROWS) - mu*mu;
    float rstd = (float)(1.0 / sqrt(var + 1e-5));
    float sc = g[f] * rstd;
    g_bnsc[f] = sc;
    g_bnsh[f] = b[f] - (float)mu * sc;
}

__global__ void bn_apply(const float* __restrict__ Z, float* __restrict__ O)
{
    int idx = blockIdx.x*256 + threadIdx.x;
    if (idx >= ROWS*DIM) return;
    int f = idx % DIM;
    O[idx] = fmaf(Z[idx], g_bnsc[f], g_bnsh[f]);
}

// ---------------- launch ----------------
static float* sym(const void* s)
{
    void* p = nullptr;
    cudaGetSymbolAddress(&p, s);
    return (float*)p;
}

extern "C" void kernel_launch(void* const* d_in, const int* in_sizes, int n_in,
                              void* d_out, int out_size)
{
    const int*   x     = (const int*)  d_in[0];
    const float* encod = (const float*)d_in[1];
    const float* embed = (const float*)d_in[2];
    const float* Wq  = (const float*)d_in[3];  const float* bq  = (const float*)d_in[4];
    const float* Wk  = (const float*)d_in[5];  const float* bk  = (const float*)d_in[6];
    const float* Wv  = (const float*)d_in[7];  const float* bv  = (const float*)d_in[8];
    const float* g1  = (const float*)d_in[9];  const float* b1  = (const float*)d_in[10];
    const float* Wq2 = (const float*)d_in[11]; const float* bq2 = (const float*)d_in[12];
    const float* Wk2 = (const float*)d_in[13]; const float* bk2 = (const float*)d_in[14];
    const float* Wv2 = (const float*)d_in[15]; const float* bv2 = (const float*)d_in[16];
    const float* Wo2 = (const float*)d_in[17]; const float* bo2 = (const float*)d_in[18];
    const float* g2  = (const float*)d_in[19]; const float* b2  = (const float*)d_in[20];
    const float* Wf  = (const float*)d_in[21]; const float* bf  = (const float*)d_in[22];
    float* out = (float*)d_out;

    float *im = sym(g_im), *q = sym(g_q), *k = sym(g_k), *v = sym(g_v);
    float *sa = sym(g_sa), *z = sym(g_z), *t1 = sym(g_t1), *v2 = sym(g_v2);
    float *av2 = sym(g_av2), *m2 = sym(g_m2), *t2 = sym(g_t2), *ff = sym(g_ff);
    float *q2 = sym(g_q2), *k2 = sym(g_k2), *S = sym(g_S), *A2 = sym(g_A2);

    const float scale1 = 1.0f / sqrtf((float)DIM);       // 1/sqrt(768)
    const float scale2 = 1.0f / sqrtf((float)HD);        // 1/8

    dim3 gemmGrid(DIM/64, ROWS/64);                      // (12, 64)
    dim3 scGrid(SEQ/64, SEQ/64, NBH);                    // (16, 16, 48)
    dim3 avGrid(SEQ/64, 1, NBH);                         // (16, 1, 48)
    dim3 bnGrid(DIM/32, 8);                              // (24, 8)
    dim3 bnBlk(32, 8);
    int ewBlocks = (ROWS*DIM + 255)/256;

    // 1) embedding + positional encoding
    embed_pos_kernel<<<ewBlocks, 256>>>(x, embed, im);

    // 2) loop-invariant cross-attention probabilities A2 = softmax(Q2 K2^T / 8)
    gemm_bias<<<gemmGrid, 256>>>(encod, DIM, 0,   Wq2, bq2, q2, DIM, DIM/2, 0);
    gemm_bias<<<gemmGrid, 256>>>(encod, DIM, 384, Wk2, bk2, k2, DIM, DIM/2, 0);
    attn_scores<<<scGrid, 256>>>(q2, k2, A2, scale2);
    softmax_rows<<<NBH*SEQ, 256>>>(A2);

    for (int li = 0; li < NITER; li++) {
        // self attention QKV (relu'd projections from thirds of input)
        gemm_bias<<<gemmGrid, 256>>>(im, DIM, 0,   Wq, bq, q, DIM, DIM/3, 1);
        gemm_bias<<<gemmGrid, 256>>>(im, DIM, 256, Wk, bk, k, DIM, DIM/3, 1);
        gemm_bias<<<gemmGrid, 256>>>(im, DIM, 512, Wv, bv, v, DIM, DIM/3, 1);
        attn_scores<<<scGrid, 256>>>(q, k, S, scale1);
        softmax_rows<<<NBH*SEQ, 256>>>(S);
        attn_av<<<avGrid, 256>>>(S, v, sa);

        // add + bn1 -> t1
        bn_zero<<<3, 256>>>();
        bn_add_stats<<<bnGrid, bnBlk>>>(im, sa, z);
        bn_finalize<<<3, 256>>>(g1, b1);
        bn_apply<<<ewBlocks, 256>>>(z, t1);

        // cross attention value path (A2 precomputed)
        gemm_bias<<<gemmGrid, 256>>>(t1, DIM, 0, Wv2, bv2, v2, DIM, DIM, 0);
        attn_av<<<avGrid, 256>>>(A2, v2, av2);
        gemm_bias<<<gemmGrid, 256>>>(av2, DIM, 0, Wo2, bo2, m2, DIM, DIM, 0);

        // add + bn2 -> t2
        bn_zero<<<3, 256>>>();
        bn_add_stats<<<bnGrid, bnBlk>>>(m2, t1, z);
        bn_finalize<<<3, 256>>>(g2, b2);
        bn_apply<<<ewBlocks, 256>>>(z, t2);

        // FFN (linear, no activation) + bn3 -> im (next layer input)
        gemm_bias<<<gemmGrid, 256>>>(t2, DIM, 0, Wf, bf, ff, DIM, DIM, 0);
        bn_zero<<<3, 256>>>();
        bn_add_stats<<<bnGrid, bnBlk>>>(t2, ff, z);
        bn_finalize<<<3, 256>>>(g2, b2);
        bn_apply<<<ewBlocks, 256>>>(z, im);
    }

    cudaMemcpyAsync(out, im, (size_t)ROWS*DIM*sizeof(float),
                    cudaMemcpyDeviceToDevice);
}

// round 3
// speedup vs baseline: 1.1295x; 1.1295x over previous
#include <cuda_runtime.h>
#include <math.h>

#define BSZ   4
#define SEQ   1024
#define DIM   768
#define NH    12
#define HD    64
#define ROWS  (BSZ*SEQ)      // 4096
#define NBH   (BSZ*NH)       // 48
#define NITER 2

// ---------------- static scratch (no allocations allowed) ----------------
__device__ float g_im [ROWS*DIM];
__device__ float g_q  [ROWS*DIM];
__device__ float g_k  [ROWS*DIM];
__device__ float g_v  [ROWS*DIM];
__device__ float g_sa [ROWS*DIM];
__device__ float g_z  [ROWS*DIM];
__device__ float g_t1 [ROWS*DIM];
__device__ float g_v2 [ROWS*DIM];
__device__ float g_av2[ROWS*DIM];
__device__ float g_m2 [ROWS*DIM];
__device__ float g_t2 [ROWS*DIM];
__device__ float g_ff [ROWS*DIM];
__device__ float g_q2 [ROWS*DIM];
__device__ float g_k2 [ROWS*DIM];
__device__ float g_S  [(size_t)NBH*SEQ*SEQ];   // self-attn scores (reused per layer)
__device__ float g_A2 [(size_t)NBH*SEQ*SEQ];   // cross-attn probs (computed ONCE)
__device__ double g_sum [DIM];
__device__ double g_sum2[DIM];
__device__ float  g_bnsc[DIM];
__device__ float  g_bnsh[DIM];

// ---------------- embedding + positional encoding ----------------
__global__ void embed_pos_kernel(const int* __restrict__ x,
                                 const float* __restrict__ embed,
                                 float* __restrict__ out)
{
    int idx = blockIdx.x * 256 + threadIdx.x;
    if (idx >= ROWS*DIM) return;
    int r = idx / DIM, d = idx - r*DIM;
    int s = r & (SEQ-1);
    int tok = x[r];
    int i = d >> 1;
    float inv = powf(10000.0f, -2.0f * (float)i / (float)DIM);
    float ang = (float)s * inv;
    float pe = (d & 1) ? cosf(ang) : sinf(ang);
    out[idx] = 2.0f * embed[(size_t)tok * DIM + d] + pe;
}

// ---------------- GEMM: C[M,N] = A[:, aoff:aoff+K] @ W[K,N] + bias ----------------
// 128x128 tile, BK=16, 256 threads, 8x8 per thread.
__global__ __launch_bounds__(256)
void gemm_bias(const float* __restrict__ A, int lda, int aoff,
               const float* __restrict__ W,
               const float* __restrict__ bias,
               float* __restrict__ C,
               int N, int K, int relu)
{
    __shared__ float As[128][20];   // row-major [m][k], pad 20 for fp4 align
    __shared__ float Bs[16][128];   // [k][n]
    int tid = threadIdx.x;
    int tx = tid & 15, ty = tid >> 4;
    int bm = blockIdx.y * 128, bn = blockIdx.x * 128;
    const float* Ab = A + (size_t)bm * lda + aoff;

    float acc[8][8];
#pragma unroll
    for (int i=0;i<8;i++)
#pragma unroll
        for (int j=0;j<8;j++) acc[i][j]=0.f;

    for (int kb = 0; kb < K; kb += 16) {
        // A tile: 128 rows x 16 k = 512 float4 -> 2 per thread
#pragma unroll
        for (int it = 0; it < 2; it++) {
            int idx = it*256 + tid;
            int r = idx >> 2, c4 = (idx & 3) * 4;
            float4 va = *reinterpret_cast<const float4*>(Ab + (size_t)r*lda + kb + c4);
            *reinterpret_cast<float4*>(&As[r][c4]) = va;
        }
        // B tile: 16 k x 128 n = 512 float4 -> 2 per thread
#pragma unroll
        for (int it = 0; it < 2; it++) {
            int idx = it*256 + tid;
            int kk = idx >> 5, n4 = (idx & 31) * 4;
            float4 vb = *reinterpret_cast<const float4*>(W + (size_t)(kb+kk)*N + bn + n4);
            *reinterpret_cast<float4*>(&Bs[kk][n4]) = vb;
        }
        __syncthreads();
#pragma unroll
        for (int k = 0; k < 16; k++) {
            float a[8], b[8];
#pragma unroll
            for (int i=0;i<8;i++) a[i] = As[ty*8+i][k];      // warp-broadcast
            float4 b0 = *reinterpret_cast<const float4*>(&Bs[k][tx*8]);
            float4 b1 = *reinterpret_cast<const float4*>(&Bs[k][tx*8+4]);
            b[0]=b0.x;b[1]=b0.y;b[2]=b0.z;b[3]=b0.w;
            b[4]=b1.x;b[5]=b1.y;b[6]=b1.z;b[7]=b1.w;
#pragma unroll
            for (int i=0;i<8;i++)
#pragma unroll
                for (int j=0;j<8;j++) acc[i][j] = fmaf(a[i], b[j], acc[i][j]);
        }
        __syncthreads();
    }
#pragma unroll
    for (int i=0;i<8;i++) {
        int m = bm + ty*8 + i;
#pragma unroll
        for (int j=0;j<8;j++) {
            int n = bn + tx*8 + j;
            float v = acc[i][j] + bias[n];
            if (relu) v = fmaxf(v, 0.f);
            C[(size_t)m*N + n] = v;
        }
    }
}

// ---------------- batched attention scores ----------------
// S[bh,q,t] = scale * sum_e Q[.,q,e]*K[.,t,e]. Tile 128x128, hd=64 resident.
// Both tiles stored k-major (transposed) -> inner loop = 4x LDS.128 + 64 FMA.
#define SC_PAD 132
#define SC_SMEM (2*64*SC_PAD*4)
__global__ __launch_bounds__(256)
void attn_scores(const float* __restrict__ Q, const float* __restrict__ K,
                 float* __restrict__ S, float scale)
{
    extern __shared__ float sm[];
    float (*Qt)[SC_PAD] = (float(*)[SC_PAD])sm;             // [k][q]
    float (*Kt)[SC_PAD] = (float(*)[SC_PAD])(sm + 64*SC_PAD); // [k][t]
    int bh = blockIdx.z;
    int b = bh / NH, h = bh - b*NH;
    int tid = threadIdx.x, tx = tid & 15, ty = tid >> 4;
    size_t base = ((size_t)b*SEQ)*DIM + h*HD;
    int q0 = blockIdx.y*128, t0 = blockIdx.x*128;

    // load + transpose: 128 rows x 16 quads = 2048 quads each -> 8 iters
#pragma unroll
    for (int it = 0; it < 8; it++) {
        int idx = it*256 + tid;
        int r  = idx >> 4;               // 0..127
        int c4 = (idx & 15) * 4;         // k quad
        float4 vq = *reinterpret_cast<const float4*>(&Q[base + (size_t)(q0+r)*DIM + c4]);
        Qt[c4+0][r]=vq.x; Qt[c4+1][r]=vq.y; Qt[c4+2][r]=vq.z; Qt[c4+3][r]=vq.w;
        float4 vk = *reinterpret_cast<const float4*>(&K[base + (size_t)(t0+r)*DIM + c4]);
        Kt[c4+0][r]=vk.x; Kt[c4+1][r]=vk.y; Kt[c4+2][r]=vk.z; Kt[c4+3][r]=vk.w;
    }
    __syncthreads();

    float acc[8][8];
#pragma unroll
    for (int i=0;i<8;i++)
#pragma unroll
        for (int j=0;j<8;j++) acc[i][j]=0.f;

#pragma unroll 8
    for (int k = 0; k < 64; k++) {
        float4 a0 = *reinterpret_cast<const float4*>(&Qt[k][ty*8]);
        float4 a1 = *reinterpret_cast<const float4*>(&Qt[k][ty*8+4]);
        float4 b0 = *reinterpret_cast<const float4*>(&Kt[k][tx*8]);
        float4 b1 = *reinterpret_cast<const float4*>(&Kt[k][tx*8+4]);
        float a[8] = {a0.x,a0.y,a0.z,a0.w,a1.x,a1.y,a1.z,a1.w};
        float b[8] = {b0.x,b0.y,b0.z,b0.w,b1.x,b1.y,b1.z,b1.w};
#pragma unroll
        for (int i=0;i<8;i++)
#pragma unroll
            for (int j=0;j<8;j++) acc[i][j] = fmaf(a[i], b[j], acc[i][j]);
    }

    float* Sp = S + (size_t)bh*SEQ*SEQ;
#pragma unroll
    for (int i=0;i<8;i++) {
        float* rowp = Sp + (size_t)(q0+ty*8+i)*SEQ + t0 + tx*8;
        float4 o0 = make_float4(acc[i][0]*scale, acc[i][1]*scale, acc[i][2]*scale, acc[i][3]*scale);
        float4 o1 = make_float4(acc[i][4]*scale, acc[i][5]*scale, acc[i][6]*scale, acc[i][7]*scale);
        *reinterpret_cast<float4*>(rowp)   = o0;
        *reinterpret_cast<float4*>(rowp+4) = o1;
    }
}

// ---------------- row softmax over last dim (SEQ=1024) ----------------
// One block (256 thr) per row; float4 I/O; shuffle + smem reductions; __expf.
__global__ __launch_bounds__(256)
void softmax_rows(float* __restrict__ S)
{
    float4* row = reinterpret_cast<float4*>(S + (size_t)blockIdx.x * SEQ);
    int t = threadIdx.x;
    __shared__ float red[8];
    float4 v = row[t];
    float m = fmaxf(fmaxf(v.x, v.y), fmaxf(v.z, v.w));
#pragma unroll
    for (int o = 16; o > 0; o >>= 1) m = fmaxf(m, __shfl_xor_sync(0xffffffffu, m, o));
    if ((t & 31) == 0) red[t >> 5] = m;
    __syncthreads();
    if (t < 8) {
        float mm = red[t];
#pragma unroll
        for (int o = 4; o > 0; o >>= 1) mm = fmaxf(mm, __shfl_xor_sync(0xffu, mm, o));
        red[t] = mm;
    }
    __syncthreads();
    m = red[0];
    __syncthreads();
    v.x = __expf(v.x - m); v.y = __expf(v.y - m);
    v.z = __expf(v.z - m); v.w = __expf(v.w - m);
    float s = v.x + v.y + v.z + v.w;
#pragma unroll
    for (int o = 16; o > 0; o >>= 1) s += __shfl_xor_sync(0xffffffffu, s, o);
    if ((t & 31) == 0) red[t >> 5] = s;
    __syncthreads();
    if (t < 8) {
        float ss = red[t];
#pragma unroll
        for (int o = 4; o > 0; o >>= 1) ss += __shfl_xor_sync(0xffu, ss, o);
        red[t] = ss;
    }
    __syncthreads();
    float inv = 1.0f / red[0];
    v.x *= inv; v.y *= inv; v.z *= inv; v.w *= inv;
    row[t] = v;
}

// ---------------- batched A @ V -> merged [B*S, DIM] layout ----------------
// Tile 128(q) x 64(n=hd), BK=32, 256 threads, 8x4 per thread.
__global__ __launch_bounds__(256)
void attn_av(const float* __restrict__ A, const float* __restrict__ V,
             float* __restrict__ O)
{
    __shared__ float As[128][36];   // [q][k] pad 36 (fp4 aligned)
    __shared__ float Vs[32][64];    // [k][n]
    int bh = blockIdx.z;
    int b = bh / NH, h = bh - b*NH;
    int tid = threadIdx.x, tx = tid & 15, ty = tid >> 4;
    int s0 = blockIdx.x * 128;
    const float* Ap = A + (size_t)bh*SEQ*SEQ;
    size_t vbase = ((size_t)b*SEQ)*DIM + h*HD;

    float acc[8][4];
#pragma unroll
    for (int i=0;i<8;i++)
#pragma unroll
        for (int j=0;j<4;j++) acc[i][j]=0.f;

    for (int t0 = 0; t0 < SEQ; t0 += 32) {
        // A tile: 128 x 32 = 1024 quads -> 4 per thread
#pragma unroll
        for (int it = 0; it < 4; it++) {
            int idx = it*256 + tid;
            int r = idx >> 3, c4 = (idx & 7) * 4;
            float4 va = *reinterpret_cast<const float4*>(Ap + (size_t)(s0+r)*SEQ + t0 + c4);
            *reinterpret_cast<float4*>(&As[r][c4]) = va;
        }
        // V tile: 32 x 64 = 512 quads -> 2 per thread
#pragma unroll
        for (int it = 0; it < 2; it++) {
            int idx = it*256 + tid;
            int kk = idx >> 4, n4 = (idx & 15) * 4;
            float4 vv = *reinterpret_cast<const float4*>(V + vbase + (size_t)(t0+kk)*DIM + n4);
            *reinterpret_cast<float4*>(&Vs[kk][n4]) = vv;
        }
        __syncthreads();
#pragma unroll 4
        for (int k = 0; k < 32; k++) {
            float a[8];
#pragma unroll
            for (int i=0;i<8;i++) a[i] = As[ty*8+i][k];     // warp-broadcast
            float4 b0 = *reinterpret_cast<const float4*>(&Vs[k][tx*4]);
            float bb[4] = {b0.x,b0.y,b0.z,b0.w};
#pragma unroll
            for (int i=0;i<8;i++)
#pragma unroll
                for (int j=0;j<4;j++) acc[i][j] = fmaf(a[i], bb[j], acc[i][j]);
        }
        __syncthreads();
    }
#pragma unroll
    for (int i=0;i<8;i++) {
        size_t orow = ((size_t)b*SEQ + s0 + ty*8 + i)*DIM + h*HD + tx*4;
        *reinterpret_cast<float4*>(&O[orow]) =
            make_float4(acc[i][0], acc[i][1], acc[i][2], acc[i][3]);
    }
}

// ---------------- batch norm (stats over all 4096 rows, per feature) ----------------
__global__ void bn_zero()
{
    int t = blockIdx.x*256 + threadIdx.x;
    if (t < DIM) { g_sum[t] = 0.0; g_sum2[t] = 0.0; }
}

__global__ __launch_bounds__(256)
void bn_add_stats(const float* __restrict__ X, const float* __restrict__ Y,
                  float* __restrict__ Z)
{
    int f  = blockIdx.x*32 + threadIdx.x;
    int rb = blockIdx.y*512;
    double s = 0.0, s2 = 0.0;
    for (int r = rb + threadIdx.y; r < rb + 512; r += 8) {
        size_t idx = (size_t)r*DIM + f;
        float v = X[idx] + Y[idx];
        Z[idx] = v;
        s += v; s2 += (double)v * (double)v;
    }
    __shared__ double sh[2][8][32];
    sh[0][threadIdx.y][threadIdx.x] = s;
    sh[1][threadIdx.y][threadIdx.x] = s2;
    __syncthreads();
    if (threadIdx.y == 0) {
        double ts = 0.0, ts2 = 0.0;
#pragma unroll
        for (int i = 0; i < 8; i++) { ts += sh[0][i][threadIdx.x]; ts2 += sh[1][i][threadIdx.x]; }
        atomicAdd(&g_sum[f], ts);
        atomicAdd(&g_sum2[f], ts2);
    }
}

__global__ void bn_finalize(const float* __restrict__ g, const float* __restrict__ b)
{
    int f = blockIdx.x*256 + threadIdx.x;
    if (f >= DIM) return;
    double mu  = g_sum[f]  * (1.0 / ROWS);
    double var = g_sum2[f] * (1.0 / ROWS) - mu*mu;
    float rstd = (float)(1.0 / sqrt(var + 1e-5));
    float sc = g[f] * rstd;
    g_bnsc[f] = sc;
    g_bnsh[f] = b[f] - (float)mu * sc;
}

__global__ void bn_apply(const float* __restrict__ Z, float* __restrict__ O)
{
    int idx = blockIdx.x*256 + threadIdx.x;
    if (idx >= ROWS*DIM) return;
    int f = idx % DIM;
    O[idx] = fmaf(Z[idx], g_bnsc[f], g_bnsh[f]);
}

// ---------------- launch ----------------
static float* sym(const void* s)
{
    void* p = nullptr;
    cudaGetSymbolAddress(&p, s);
    return (float*)p;
}

extern "C" void kernel_launch(void* const* d_in, const int* in_sizes, int n_in,
                              void* d_out, int out_size)
{
    const int*   x     = (const int*)  d_in[0];
    const float* encod = (const float*)d_in[1];
    const float* embed = (const float*)d_in[2];
    const float* Wq  = (const float*)d_in[3];  const float* bq  = (const float*)d_in[4];
    const float* Wk  = (const float*)d_in[5];  const float* bk  = (const float*)d_in[6];
    const float* Wv  = (const float*)d_in[7];  const float* bv  = (const float*)d_in[8];
    const float* g1  = (const float*)d_in[9];  const float* b1  = (const float*)d_in[10];
    const float* Wq2 = (const float*)d_in[11]; const float* bq2 = (const float*)d_in[12];
    const float* Wk2 = (const float*)d_in[13]; const float* bk2 = (const float*)d_in[14];
    const float* Wv2 = (const float*)d_in[15]; const float* bv2 = (const float*)d_in[16];
    const float* Wo2 = (const float*)d_in[17]; const float* bo2 = (const float*)d_in[18];
    const float* g2  = (const float*)d_in[19]; const float* b2  = (const float*)d_in[20];
    const float* Wf  = (const float*)d_in[21]; const float* bf  = (const float*)d_in[22];
    float* out = (float*)d_out;

    float *im = sym(g_im), *q = sym(g_q), *k = sym(g_k), *v = sym(g_v);
    float *sa = sym(g_sa), *z = sym(g_z), *t1 = sym(g_t1), *v2 = sym(g_v2);
    float *av2 = sym(g_av2), *m2 = sym(g_m2), *t2 = sym(g_t2), *ff = sym(g_ff);
    float *q2 = sym(g_q2), *k2 = sym(g_k2), *S = sym(g_S), *A2 = sym(g_A2);

    cudaFuncSetAttribute(attn_scores, cudaFuncAttributeMaxDynamicSharedMemorySize, SC_SMEM);

    const float scale1 = 1.0f / sqrtf((float)DIM);       // 1/sqrt(768)
    const float scale2 = 1.0f / sqrtf((float)HD);        // 1/8

    dim3 gemmGrid(DIM/128, ROWS/128);                    // (6, 32)
    dim3 scGrid(SEQ/128, SEQ/128, NBH);                  // (8, 8, 48)
    dim3 avGrid(SEQ/128, 1, NBH);                        // (8, 1, 48)
    dim3 bnGrid(DIM/32, 8);                              // (24, 8)
    dim3 bnBlk(32, 8);
    int ewBlocks = (ROWS*DIM + 255)/256;

    // 1) embedding + positional encoding
    embed_pos_kernel<<<ewBlocks, 256>>>(x, embed, im);

    // 2) loop-invariant cross-attention probabilities A2 = softmax(Q2 K2^T / 8)
    gemm_bias<<<gemmGrid, 256>>>(encod, DIM, 0,   Wq2, bq2, q2, DIM, DIM/2, 0);
    gemm_bias<<<gemmGrid, 256>>>(encod, DIM, 384, Wk2, bk2, k2, DIM, DIM/2, 0);
    attn_scores<<<scGrid, 256, SC_SMEM>>>(q2, k2, A2, scale2);
    softmax_rows<<<NBH*SEQ, 256>>>(A2);

    for (int li = 0; li < NITER; li++) {
        // self attention QKV (relu'd projections from thirds of input)
        gemm_bias<<<gemmGrid, 256>>>(im, DIM, 0,   Wq, bq, q, DIM, DIM/3, 1);
        gemm_bias<<<gemmGrid, 256>>>(im, DIM, 256, Wk, bk, k, DIM, DIM/3, 1);
        gemm_bias<<<gemmGrid, 256>>>(im, DIM, 512, Wv, bv, v, DIM, DIM/3, 1);
        attn_scores<<<scGrid, 256, SC_SMEM>>>(q, k, S, scale1);
        softmax_rows<<<NBH*SEQ, 256>>>(S);
        attn_av<<<avGrid, 256>>>(S, v, sa);

        // add + bn1 -> t1
        bn_zero<<<3, 256>>>();
        bn_add_stats<<<bnGrid, bnBlk>>>(im, sa, z);
        bn_finalize<<<3, 256>>>(g1, b1);
        bn_apply<<<ewBlocks, 256>>>(z, t1);

        // cross attention value path (A2 precomputed)
        gemm_bias<<<gemmGrid, 256>>>(t1, DIM, 0, Wv2, bv2, v2, DIM, DIM, 0);
        attn_av<<<avGrid, 256>>>(A2, v2, av2);
        gemm_bias<<<gemmGrid, 256>>>(av2, DIM, 0, Wo2, bo2, m2, DIM, DIM, 0);

        // add + bn2 -> t2
        bn_zero<<<3, 256>>>();
        bn_add_stats<<<bnGrid, bnBlk>>>(m2, t1, z);
        bn_finalize<<<3, 256>>>(g2, b2);
        bn_apply<<<ewBlocks, 256>>>(z, t2);

        // FFN (linear) + bn3 -> im (next layer input)
        gemm_bias<<<gemmGrid, 256>>>(t2, DIM, 0, Wf, bf, ff, DIM, DIM, 0);
        bn_zero<<<3, 256>>>();
        bn_add_stats<<<bnGrid, bnBlk>>>(t2, ff, z);
        bn_finalize<<<3, 256>>>(g2, b2);
        bn_apply<<<ewBlocks, 256>>>(z, im);
    }

    cudaMemcpyAsync(out, im, (size_t)ROWS*DIM*sizeof(float),
                    cudaMemcpyDeviceToDevice);
}

// round 5
// speedup vs baseline: 1.1865x; 1.0504x over previous
#include <cuda_runtime.h>
#include <math.h>

#define BSZ   4
#define SEQ   1024
#define DIM   768
#define NH    12
#define HD    64
#define ROWS  (BSZ*SEQ)      // 4096
#define NBH   (BSZ*NH)       // 48
#define NITER 2

// ---------------- static scratch (no allocations allowed) ----------------
__device__ float g_im [ROWS*DIM];
__device__ float g_q  [ROWS*DIM];
__device__ float g_k  [ROWS*DIM];
__device__ float g_v  [ROWS*DIM];
__device__ float g_sa [ROWS*DIM];
__device__ float g_z  [ROWS*DIM];
__device__ float g_t1 [ROWS*DIM];
__device__ float g_v2 [ROWS*DIM];
__device__ float g_av2[ROWS*DIM];
__device__ float g_m2 [ROWS*DIM];
__device__ float g_t2 [ROWS*DIM];
__device__ float g_ff [ROWS*DIM];
__device__ float g_q2 [ROWS*DIM];
__device__ float g_k2 [ROWS*DIM];
__device__ float g_S  [(size_t)NBH*SEQ*SEQ];   // self-attn scores (reused per layer)
__device__ float g_A2 [(size_t)NBH*SEQ*SEQ];   // cross-attn probs (computed ONCE)
__device__ double g_sum [DIM];
__device__ double g_sum2[DIM];
__device__ float  g_bnsc[DIM];
__device__ float  g_bnsh[DIM];

// ---------------- fast exp: no MUFU, pure FMA/ALU pipes ----------------
// valid for x in [-87, 0]; rel err ~2e-6 (deg-5 poly on [-0.5,0.5])
__device__ __forceinline__ float fast_exp(float x)
{
    float t = fmaxf(x * 1.4426950408889634f, -120.0f);   // log2(e), clamp underflow
    float r = t + 12582912.0f;                           // round-to-nearest (1.5*2^23)
    float nf = r - 12582912.0f;
    float f = t - nf;                                    // f in [-0.5, 0.5]
    float p = 1.3333558146e-3f;
    p = fmaf(p, f, 9.6181291077e-3f);
    p = fmaf(p, f, 5.5504108664e-2f);
    p = fmaf(p, f, 2.4022650695e-1f);
    p = fmaf(p, f, 6.9314718056e-1f);
    p = fmaf(p, f, 1.0f);
    int n = __float_as_int(r) - 0x4B400000;              // integer part of t
    return __int_as_float(__float_as_int(p) + (n << 23));
}

// ---------------- embedding + positional encoding ----------------
__global__ void embed_pos_kernel(const int* __restrict__ x,
                                 const float* __restrict__ embed,
                                 float* __restrict__ out)
{
    int idx = blockIdx.x * 256 + threadIdx.x;
    if (idx >= ROWS*DIM) return;
    int r = idx / DIM, d = idx - r*DIM;
    int s = r & (SEQ-1);
    int tok = x[r];
    int i = d >> 1;
    // 10000^(-2i/D) = 2^(-i * log2(1e4) * 2/D)
    float inv = exp2f((float)i * (-13.287712379549449f * 2.0f / (float)DIM));
    float ang = (float)s * inv;
    float pe = (d & 1) ? cosf(ang) : sinf(ang);
    out[idx] = 2.0f * embed[(size_t)tok * DIM + d] + pe;
}

// ---------------- GEMM: C[M,N] = A[:, aoff:aoff+K] @ W[K,N] + bias ----------------
// 128x128 tile, BK=16, 256 threads, 8x8 per thread, double-buffered smem.
__global__ __launch_bounds__(256)
void gemm_bias(const float* __restrict__ A, int lda, int aoff,
               const float* __restrict__ W,
               const float* __restrict__ bias,
               float* __restrict__ C,
               int N, int K, int relu)
{
    __shared__ float As[2][128][20];   // [buf][m][k]
    __shared__ float Bs[2][16][128];   // [buf][k][n]
    int tid = threadIdx.x;
    int tx = tid & 15, ty = tid >> 4;
    int bm = blockIdx.y * 128, bn = blockIdx.x * 128;
    const float* Ab = A + (size_t)bm * lda + aoff;

    // loader coords (2 float4 each for A and B)
    int ar0 = tid >> 2,        ac0 = (tid & 3) * 4;
    int ar1 = (256+tid) >> 2,  ac1 = ac0;
    int bk0 = tid >> 5,        bn0 = (tid & 31) * 4;
    int bk1 = (256+tid) >> 5,  bn1 = bn0;

    float acc[8][8];
#pragma unroll
    for (int i=0;i<8;i++)
#pragma unroll
        for (int j=0;j<8;j++) acc[i][j]=0.f;

    // prologue: stage 0
    *reinterpret_cast<float4*>(&As[0][ar0][ac0]) = *reinterpret_cast<const float4*>(Ab + (size_t)ar0*lda + ac0);
    *reinterpret_cast<float4*>(&As[0][ar1][ac1]) = *reinterpret_cast<const float4*>(Ab + (size_t)ar1*lda + ac1);
    *reinterpret_cast<float4*>(&Bs[0][bk0][bn0]) = *reinterpret_cast<const float4*>(W + (size_t)bk0*N + bn + bn0);
    *reinterpret_cast<float4*>(&Bs[0][bk1][bn1]) = *reinterpret_cast<const float4*>(W + (size_t)bk1*N + bn + bn1);
    __syncthreads();

    int buf = 0;
    for (int kb = 0; kb < K; kb += 16) {
        float4 pa0, pa1, pb0, pb1;
        bool more = (kb + 16) < K;
        if (more) {
            pa0 = *reinterpret_cast<const float4*>(Ab + (size_t)ar0*lda + kb+16 + ac0);
            pa1 = *reinterpret_cast<const float4*>(Ab + (size_t)ar1*lda + kb+16 + ac1);
            pb0 = *reinterpret_cast<const float4*>(W + (size_t)(kb+16+bk0)*N + bn + bn0);
            pb1 = *reinterpret_cast<const float4*>(W + (size_t)(kb+16+bk1)*N + bn + bn1);
        }
#pragma unroll
        for (int k = 0; k < 16; k++) {
            float a[8], b[8];
#pragma unroll
            for (int i=0;i<8;i++) a[i] = As[buf][ty*8+i][k];   // warp-broadcast
            float4 b0 = *reinterpret_cast<const float4*>(&Bs[buf][k][tx*8]);
            float4 b1 = *reinterpret_cast<const float4*>(&Bs[buf][k][tx*8+4]);
            b[0]=b0.x;b[1]=b0.y;b[2]=b0.z;b[3]=b0.w;
            b[4]=b1.x;b[5]=b1.y;b[6]=b1.z;b[7]=b1.w;
#pragma unroll
            for (int i=0;i<8;i++)
#pragma unroll
                for (int j=0;j<8;j++) acc[i][j] = fmaf(a[i], b[j], acc[i][j]);
        }
        if (more) {
            int nb = buf ^ 1;
            *reinterpret_cast<float4*>(&As[nb][ar0][ac0]) = pa0;
            *reinterpret_cast<float4*>(&As[nb][ar1][ac1]) = pa1;
            *reinterpret_cast<float4*>(&Bs[nb][bk0][bn0]) = pb0;
            *reinterpret_cast<float4*>(&Bs[nb][bk1][bn1]) = pb1;
        }
        __syncthreads();
        buf ^= 1;
    }
#pragma unroll
    for (int i=0;i<8;i++) {
        int m = bm + ty*8 + i;
#pragma unroll
        for (int j=0;j<8;j++) {
            int n = bn + tx*8 + j;
            float v = acc[i][j] + bias[n];
            if (relu) v = fmaxf(v, 0.f);
            C[(size_t)m*N + n] = v;
        }
    }
}

// ---------------- batched attention scores ----------------
// S[bh,q,t] = scale * sum_e Q[.,q,e]*K[.,t,e]. Tile 128x128, hd=64 resident.
#define SC_PAD 132
#define SC_SMEM (2*64*SC_PAD*4)
__global__ __launch_bounds__(256)
void attn_scores(const float* __restrict__ Q, const float* __restrict__ K,
                 float* __restrict__ S, float scale)
{
    extern __shared__ float sm[];
    float (*Qt)[SC_PAD] = (float(*)[SC_PAD])sm;               // [k][q]
    float (*Kt)[SC_PAD] = (float(*)[SC_PAD])(sm + 64*SC_PAD); // [k][t]
    int bh = blockIdx.z;
    int b = bh / NH, h = bh - b*NH;
    int tid = threadIdx.x, tx = tid & 15, ty = tid >> 4;
    size_t base = ((size_t)b*SEQ)*DIM + h*HD;
    int q0 = blockIdx.y*128, t0 = blockIdx.x*128;

#pragma unroll
    for (int it = 0; it < 8; it++) {
        int idx = it*256 + tid;
        int r  = idx >> 4;
        int c4 = (idx & 15) * 4;
        float4 vq = *reinterpret_cast<const float4*>(&Q[base + (size_t)(q0+r)*DIM + c4]);
        Qt[c4+0][r]=vq.x; Qt[c4+1][r]=vq.y; Qt[c4+2][r]=vq.z; Qt[c4+3][r]=vq.w;
        float4 vk = *reinterpret_cast<const float4*>(&K[base + (size_t)(t0+r)*DIM + c4]);
        Kt[c4+0][r]=vk.x; Kt[c4+1][r]=vk.y; Kt[c4+2][r]=vk.z; Kt[c4+3][r]=vk.w;
    }
    __syncthreads();

    float acc[8][8];
#pragma unroll
    for (int i=0;i<8;i++)
#pragma unroll
        for (int j=0;j<8;j++) acc[i][j]=0.f;

#pragma unroll 8
    for (int k = 0; k < 64; k++) {
        float4 a0 = *reinterpret_cast<const float4*>(&Qt[k][ty*8]);
        float4 a1 = *reinterpret_cast<const float4*>(&Qt[k][ty*8+4]);
        float4 b0 = *reinterpret_cast<const float4*>(&Kt[k][tx*8]);
        float4 b1 = *reinterpret_cast<const float4*>(&Kt[k][tx*8+4]);
        float a[8] = {a0.x,a0.y,a0.z,a0.w,a1.x,a1.y,a1.z,a1.w};
        float b[8] = {b0.x,b0.y,b0.z,b0.w,b1.x,b1.y,b1.z,b1.w};
#pragma unroll
        for (int i=0;i<8;i++)
#pragma unroll
            for (int j=0;j<8;j++) acc[i][j] = fmaf(a[i], b[j], acc[i][j]);
    }

    float* Sp = S + (size_t)bh*SEQ*SEQ;
#pragma unroll
    for (int i=0;i<8;i++) {
        float* rowp = Sp + (size_t)(q0+ty*8+i)*SEQ + t0 + tx*8;
        float4 o0 = make_float4(acc[i][0]*scale, acc[i][1]*scale, acc[i][2]*scale, acc[i][3]*scale);
        float4 o1 = make_float4(acc[i][4]*scale, acc[i][5]*scale, acc[i][6]*scale, acc[i][7]*scale);
        *reinterpret_cast<float4*>(rowp)   = o0;
        *reinterpret_cast<float4*>(rowp+4) = o1;
    }
}

// ---------------- row softmax over last dim (SEQ=1024) ----------------
__global__ __launch_bounds__(256)
void softmax_rows(float* __restrict__ S)
{
    float4* row = reinterpret_cast<float4*>(S + (size_t)blockIdx.x * SEQ);
    int t = threadIdx.x;
    __shared__ float red[8];
    float4 v = row[t];
    float m = fmaxf(fmaxf(v.x, v.y), fmaxf(v.z, v.w));
#pragma unroll
    for (int o = 16; o > 0; o >>= 1) m = fmaxf(m, __shfl_xor_sync(0xffffffffu, m, o));
    if ((t & 31) == 0) red[t >> 5] = m;
    __syncthreads();
    if (t < 8) {
        float mm = red[t];
#pragma unroll
        for (int o = 4; o > 0; o >>= 1) mm = fmaxf(mm, __shfl_xor_sync(0xffu, mm, o));
        red[t] = mm;
    }
    __syncthreads();
    m = red[0];
    __syncthreads();
    v.x = fast_exp(v.x - m); v.y = fast_exp(v.y - m);
    v.z = fast_exp(v.z - m); v.w = fast_exp(v.w - m);
    float s = v.x + v.y + v.z + v.w;
#pragma unroll
    for (int o = 16; o > 0; o >>= 1) s += __shfl_xor_sync(0xffffffffu, s, o);
    if ((t & 31) == 0) red[t >> 5] = s;
    __syncthreads();
    if (t < 8) {
        float ss = red[t];
#pragma unroll
        for (int o = 4; o > 0; o >>= 1) ss += __shfl_xor_sync(0xffu, ss, o);
        red[t] = ss;
    }
    __syncthreads();
    float inv = 1.0f / red[0];
    v.x *= inv; v.y *= inv; v.z *= inv; v.w *= inv;
    row[t] = v;
}

// ---------------- batched A @ V -> merged [B*S, DIM] layout ----------------
__global__ __launch_bounds__(256)
void attn_av(const float* __restrict__ A, const float* __restrict__ V,
             float* __restrict__ O)
{
    __shared__ float As[128][36];
    __shared__ float Vs[32][64];
    int bh = blockIdx.z;
    int b = bh / NH, h = bh - b*NH;
    int tid = threadIdx.x, tx = tid & 15, ty = tid >> 4;
    int s0 = blockIdx.x * 128;
    const float* Ap = A + (size_t)bh*SEQ*SEQ;
    size_t vbase = ((size_t)b*SEQ)*DIM + h*HD;

    float acc[8][4];
#pragma unroll
    for (int i=0;i<8;i++)
#pragma unroll
        for (int j=0;j<4;j++) acc[i][j]=0.f;

    for (int t0 = 0; t0 < SEQ; t0 += 32) {
#pragma unroll
        for (int it = 0; it < 4; it++) {
            int idx = it*256 + tid;
            int r = idx >> 3, c4 = (idx & 7) * 4;
            float4 va = *reinterpret_cast<const float4*>(Ap + (size_t)(s0+r)*SEQ + t0 + c4);
            *reinterpret_cast<float4*>(&As[r][c4]) = va;
        }
#pragma unroll
        for (int it = 0; it < 2; it++) {
            int idx = it*256 + tid;
            int kk = idx >> 4, n4 = (idx & 15) * 4;
            float4 vv = *reinterpret_cast<const float4*>(V + vbase + (size_t)(t0+kk)*DIM + n4);
            *reinterpret_cast<float4*>(&Vs[kk][n4]) = vv;
        }
        __syncthreads();
#pragma unroll 4
        for (int k = 0; k < 32; k++) {
            float a[8];
#pragma unroll
            for (int i=0;i<8;i++) a[i] = As[ty*8+i][k];
            float4 b0 = *reinterpret_cast<const float4*>(&Vs[k][tx*4]);
            float bb[4] = {b0.x,b0.y,b0.z,b0.w};
#pragma unroll
            for (int i=0;i<8;i++)
#pragma unroll
                for (int j=0;j<4;j++) acc[i][j] = fmaf(a[i], bb[j], acc[i][j]);
        }
        __syncthreads();
    }
#pragma unroll
    for (int i=0;i<8;i++) {
        size_t orow = ((size_t)b*SEQ + s0 + ty*8 + i)*DIM + h*HD + tx*4;
        *reinterpret_cast<float4*>(&O[orow]) =
            make_float4(acc[i][0], acc[i][1], acc[i][2], acc[i][3]);
    }
}

// ---------------- batch norm ----------------
__global__ void bn_zero()
{
    int t = blockIdx.x*256 + threadIdx.x;
    if (t < DIM) { g_sum[t] = 0.0; g_sum2[t] = 0.0; }
}

// z = x + y; fp32 thread-local sums (64 elems each), double cross-thread reduce.
__global__ __launch_bounds__(256)
void bn_add_stats(const float* __restrict__ X, const float* __restrict__ Y,
                  float* __restrict__ Z)
{
    int f  = blockIdx.x*32 + threadIdx.x;
    int rb = blockIdx.y*512;
    float s = 0.0f, s2 = 0.0f;
    for (int r = rb + threadIdx.y; r < rb + 512; r += 8) {
        size_t idx = (size_t)r*DIM + f;
        float v = X[idx] + Y[idx];
        Z[idx] = v;
        s += v; s2 = fmaf(v, v, s2);
    }
    __shared__ double sh[2][8][32];
    sh[0][threadIdx.y][threadIdx.x] = (double)s;
    sh[1][threadIdx.y][threadIdx.x] = (double)s2;
    __syncthreads();
    if (threadIdx.y == 0) {
        double ts = 0.0, ts2 = 0.0;
#pragma unroll
        for (int i = 0; i < 8; i++) { ts += sh[0][i][threadIdx.x]; ts2 += sh[1][i][threadIdx.x]; }
        atomicAdd(&g_sum[f], ts);
        atomicAdd(&g_sum2[f], ts2);
    }
}

__global__ void bn_finalize(const float* __restrict__ g, const float* __restrict__ b)
{
    int f = blockIdx.x*256 + threadIdx.x;
    if (f >= DIM) return;
    double mu  = g_sum[f]  * (1.0 / ROWS);
    double var = g_sum2[f] * (1.0 / ROWS) - mu*mu;
    float rstd = (float)(1.0 / sqrt(var + 1e-5));
    float sc = g[f] * rstd;
    g_bnsc[f] = sc;
    g_bnsh[f] = b[f] - (float)mu * sc;
}

__global__ void bn_apply(const float* __restrict__ Z, float* __restrict__ O)
{
    int idx = blockIdx.x*256 + threadIdx.x;
    if (idx >= ROWS*DIM) return;
    int f = idx % DIM;
    O[idx] = fmaf(Z[idx], g_bnsc[f], g_bnsh[f]);
}

// ---------------- launch ----------------
static float* sym(const void* s)
{
    void* p = nullptr;
    cudaGetSymbolAddress(&p, s);
    return (float*)p;
}

extern "C" void kernel_launch(void* const* d_in, const int* in_sizes, int n_in,
                              void* d_out, int out_size)
{
    const int*   x     = (const int*)  d_in[0];
    const float* encod = (const float*)d_in[1];
    const float* embed = (const float*)d_in[2];
    const float* Wq  = (const float*)d_in[3];  const float* bq  = (const float*)d_in[4];
    const float* Wk  = (const float*)d_in[5];  const float* bk  = (const float*)d_in[6];
    const float* Wv  = (const float*)d_in[7];  const float* bv  = (const float*)d_in[8];
    const float* g1  = (const float*)d_in[9];  const float* b1  = (const float*)d_in[10];
    const float* Wq2 = (const float*)d_in[11]; const float* bq2 = (const float*)d_in[12];
    const float* Wk2 = (const float*)d_in[13]; const float* bk2 = (const float*)d_in[14];
    const float* Wv2 = (const float*)d_in[15]; const float* bv2 = (const float*)d_in[16];
    const float* Wo2 = (const float*)d_in[17]; const float* bo2 = (const float*)d_in[18];
    const float* g2  = (const float*)d_in[19]; const float* b2  = (const float*)d_in[20];
    const float* Wf  = (const float*)d_in[21]; const float* bf  = (const float*)d_in[22];
    float* out = (float*)d_out;

    float *im = sym(g_im), *q = sym(g_q), *k = sym(g_k), *v = sym(g_v);
    float *sa = sym(g_sa), *z = sym(g_z), *t1 = sym(g_t1), *v2 = sym(g_v2);
    float *av2 = sym(g_av2), *m2 = sym(g_m2), *t2 = sym(g_t2), *ff = sym(g_ff);
    float *q2 = sym(g_q2), *k2 = sym(g_k2), *S = sym(g_S), *A2 = sym(g_A2);

    cudaFuncSetAttribute(attn_scores, cudaFuncAttributeMaxDynamicSharedMemorySize, SC_SMEM);

    const float scale1 = 1.0f / sqrtf((float)DIM);
    const float scale2 = 1.0f / sqrtf((float)HD);

    dim3 gemmGrid(DIM/128, ROWS/128);
    dim3 scGrid(SEQ/128, SEQ/128, NBH);
    dim3 avGrid(SEQ/128, 1, NBH);
    dim3 bnGrid(DIM/32, 8);
    dim3 bnBlk(32, 8);
    int ewBlocks = (ROWS*DIM + 255)/256;

    embed_pos_kernel<<<ewBlocks, 256>>>(x, embed, im);

    // loop-invariant cross-attention probabilities
    gemm_bias<<<gemmGrid, 256>>>(encod, DIM, 0,   Wq2, bq2, q2, DIM, DIM/2, 0);
    gemm_bias<<<gemmGrid, 256>>>(encod, DIM, 384, Wk2, bk2, k2, DIM, DIM/2, 0);
    attn_scores<<<scGrid, 256, SC_SMEM>>>(q2, k2, A2, scale2);
    softmax_rows<<<NBH*SEQ, 256>>>(A2);

    for (int li = 0; li < NITER; li++) {
        gemm_bias<<<gemmGrid, 256>>>(im, DIM, 0,   Wq, bq, q, DIM, DIM/3, 1);
        gemm_bias<<<gemmGrid, 256>>>(im, DIM, 256, Wk, bk, k, DIM, DIM/3, 1);
        gemm_bias<<<gemmGrid, 256>>>(im, DIM, 512, Wv, bv, v, DIM, DIM/3, 1);
        attn_scores<<<scGrid, 256, SC_SMEM>>>(q, k, S, scale1);
        softmax_rows<<<NBH*SEQ, 256>>>(S);
        attn_av<<<avGrid, 256>>>(S, v, sa);

        bn_zero<<<3, 256>>>();
        bn_add_stats<<<bnGrid, bnBlk>>>(im, sa, z);
        bn_finalize<<<3, 256>>>(g1, b1);
        bn_apply<<<ewBlocks, 256>>>(z, t1);

        gemm_bias<<<gemmGrid, 256>>>(t1, DIM, 0, Wv2, bv2, v2, DIM, DIM, 0);
        attn_av<<<avGrid, 256>>>(A2, v2, av2);
        gemm_bias<<<gemmGrid, 256>>>(av2, DIM, 0, Wo2, bo2, m2, DIM, DIM, 0);

        bn_zero<<<3, 256>>>();
        bn_add_stats<<<bnGrid, bnBlk>>>(m2, t1, z);
        bn_finalize<<<3, 256>>>(g2, b2);
        bn_apply<<<ewBlocks, 256>>>(z, t2);

        gemm_bias<<<gemmGrid, 256>>>(t2, DIM, 0, Wf, bf, ff, DIM, DIM, 0);
        bn_zero<<<3, 256>>>();
        bn_add_stats<<<bnGrid, bnBlk>>>(t2, ff, z);
        bn_finalize<<<3, 256>>>(g2, b2);
        bn_apply<<<ewBlocks, 256>>>(z, im);
    }

    cudaMemcpyAsync(out, im, (size_t)ROWS*DIM*sizeof(float),
                    cudaMemcpyDeviceToDevice);
}

// round 6
// speedup vs baseline: 1.8307x; 1.5429x over previous
#include <cuda_runtime.h>
#include <cuda_bf16.h>
#include <math.h>

#define BSZ   4
#define SEQ   1024
#define DIM   768
#define NH    12
#define HD    64
#define ROWS  (BSZ*SEQ)      // 4096
#define NBH   (BSZ*NH)       // 48
#define NITER 2

typedef unsigned short u16;
typedef unsigned int   u32;

// ---------------- static scratch (no allocations allowed) ----------------
__device__ float g_im [ROWS*DIM];
__device__ float g_q  [ROWS*DIM];
__device__ float g_k  [ROWS*DIM];
__device__ float g_v  [ROWS*DIM];
__device__ float g_sa [ROWS*DIM];
__device__ float g_z  [ROWS*DIM];
__device__ float g_t1 [ROWS*DIM];
__device__ float g_v2 [ROWS*DIM];
__device__ float g_av2[ROWS*DIM];
__device__ float g_m2 [ROWS*DIM];
__device__ float g_t2 [ROWS*DIM];
__device__ float g_ff [ROWS*DIM];
__device__ float g_q2 [ROWS*DIM];
__device__ float g_k2 [ROWS*DIM];
__device__ float g_S  [(size_t)NBH*SEQ*SEQ];
__device__ float g_A2 [(size_t)NBH*SEQ*SEQ];
__device__ double g_sum [DIM];
__device__ double g_sum2[DIM];
__device__ float  g_bnsc[DIM];
__device__ float  g_bnsh[DIM];

// ---------------- helpers ----------------
__device__ __forceinline__ void bsplit(float x, u16& h, u16& l)
{
    __nv_bfloat16 bh = __float2bfloat16(x);
    h = __bfloat16_as_ushort(bh);
    l = __bfloat16_as_ushort(__float2bfloat16(x - __bfloat162float(bh)));
}
__device__ __forceinline__ u32 pk(u16 a, u16 b) { return (u32)a | ((u32)b << 16); }

__device__ __forceinline__ void mma_bf16(float d[4], u32 a0, u32 a1, u32 a2, u32 a3,
                                         u32 b0, u32 b1)
{
    asm volatile(
        "mma.sync.aligned.m16n8k16.row.col.f32.bf16.bf16.f32 "
        "{%0,%1,%2,%3}, {%4,%5,%6,%7}, {%8,%9}, {%0,%1,%2,%3};\n"
        : "+f"(d[0]), "+f"(d[1]), "+f"(d[2]), "+f"(d[3])
        : "r"(a0), "r"(a1), "r"(a2), "r"(a3), "r"(b0), "r"(b1));
}

// fast exp: pure FMA/ALU (no MUFU); x in [-87,0], rel err ~2e-6
__device__ __forceinline__ float fast_exp(float x)
{
    float t = fmaxf(x * 1.4426950408889634f, -120.0f);
    float r = t + 12582912.0f;
    float nf = r - 12582912.0f;
    float f = t - nf;
    float p = 1.3333558146e-3f;
    p = fmaf(p, f, 9.6181291077e-3f);
    p = fmaf(p, f, 5.5504108664e-2f);
    p = fmaf(p, f, 2.4022650695e-1f);
    p = fmaf(p, f, 6.9314718056e-1f);
    p = fmaf(p, f, 1.0f);
    int n = __float_as_int(r) - 0x4B400000;
    return __int_as_float(__float_as_int(p) + (n << 23));
}

// ---------------- embedding + positional encoding ----------------
__global__ void embed_pos_kernel(const int* __restrict__ x,
                                 const float* __restrict__ embed,
                                 float* __restrict__ out)
{
    int idx = blockIdx.x * 256 + threadIdx.x;
    if (idx >= ROWS*DIM) return;
    int r = idx / DIM, d = idx - r*DIM;
    int s = r & (SEQ-1);
    int tok = x[r];
    int i = d >> 1;
    float inv = exp2f((float)i * (-13.287712379549449f * 2.0f / (float)DIM));
    float ang = (float)s * inv;
    float pe = (d & 1) ? cosf(ang) : sinf(ang);
    out[idx] = 2.0f * embed[(size_t)tok * DIM + d] + pe;
}

// ---------------- tensor GEMM: C[M,N] = A[:, aoff:+K] @ W[K,N] + bias ----------------
// 128x128 block, BK=32, 8 warps (2m x 4n), warp tile 64x32, bf16-split 3-term.
#define GA_RS 40
#define GB_RS 136
__global__ __launch_bounds__(256)
void gemm_bias_t(const float* __restrict__ A, int lda, int aoff,
                 const float* __restrict__ W,
                 const float* __restrict__ bias,
                 float* __restrict__ C,
                 int N, int K, int relu)
{
    __shared__ u16 Ah[128*GA_RS], Al[128*GA_RS];
    __shared__ u16 Bh[32*GB_RS],  Bl[32*GB_RS];
    int tid = threadIdx.x;
    int lane = tid & 31, wid = tid >> 5;
    int wm = wid & 1, wn = wid >> 1;
    int bm = blockIdx.y*128, bn = blockIdx.x*128;
    const float* Ab = A + (size_t)bm*lda + aoff;

    float acc[4][4][4];
#pragma unroll
    for (int i=0;i<4;i++)
#pragma unroll
        for (int j=0;j<4;j++)
#pragma unroll
            for (int q=0;q<4;q++) acc[i][j][q]=0.f;

    for (int kb = 0; kb < K; kb += 32) {
        // A tile 128x32
#pragma unroll
        for (int it = 0; it < 4; it++) {
            int idx = it*256 + tid;
            int r = idx >> 3, c4 = (idx & 7) * 4;
            float4 v = *reinterpret_cast<const float4*>(Ab + (size_t)r*lda + kb + c4);
            u16 h0,l0,h1,l1,h2,l2,h3,l3;
            bsplit(v.x,h0,l0); bsplit(v.y,h1,l1); bsplit(v.z,h2,l2); bsplit(v.w,h3,l3);
            *reinterpret_cast<u32*>(&Ah[r*GA_RS + c4])     = pk(h0,h1);
            *reinterpret_cast<u32*>(&Ah[r*GA_RS + c4 + 2]) = pk(h2,h3);
            *reinterpret_cast<u32*>(&Al[r*GA_RS + c4])     = pk(l0,l1);
            *reinterpret_cast<u32*>(&Al[r*GA_RS + c4 + 2]) = pk(l2,l3);
        }
        // B tile 32x128 (natural [k][n])
#pragma unroll
        for (int it = 0; it < 4; it++) {
            int idx = it*256 + tid;
            int kk = idx >> 5, n4 = (idx & 31) * 4;
            float4 v = *reinterpret_cast<const float4*>(W + (size_t)(kb+kk)*N + bn + n4);
            u16 h0,l0,h1,l1,h2,l2,h3,l3;
            bsplit(v.x,h0,l0); bsplit(v.y,h1,l1); bsplit(v.z,h2,l2); bsplit(v.w,h3,l3);
            *reinterpret_cast<u32*>(&Bh[kk*GB_RS + n4])     = pk(h0,h1);
            *reinterpret_cast<u32*>(&Bh[kk*GB_RS + n4 + 2]) = pk(h2,h3);
            *reinterpret_cast<u32*>(&Bl[kk*GB_RS + n4])     = pk(l0,l1);
            *reinterpret_cast<u32*>(&Bl[kk*GB_RS + n4 + 2]) = pk(l2,l3);
        }
        __syncthreads();
#pragma unroll
        for (int ks = 0; ks < 32; ks += 16) {
            u32 bhf[4][2], blf[4][2];
#pragma unroll
            for (int nf = 0; nf < 4; nf++) {
                int n  = wn*32 + nf*8 + (lane >> 2);
                int k0 = ks + (lane & 3)*2;
                bhf[nf][0] = pk(Bh[k0*GB_RS+n],     Bh[(k0+1)*GB_RS+n]);
                bhf[nf][1] = pk(Bh[(k0+8)*GB_RS+n], Bh[(k0+9)*GB_RS+n]);
                blf[nf][0] = pk(Bl[k0*GB_RS+n],     Bl[(k0+1)*GB_RS+n]);
                blf[nf][1] = pk(Bl[(k0+8)*GB_RS+n], Bl[(k0+9)*GB_RS+n]);
            }
#pragma unroll
            for (int mf = 0; mf < 4; mf++) {
                int r = wm*64 + mf*16 + (lane >> 2);
                int c = ks + (lane & 3)*2;
                u32 ah0 = *reinterpret_cast<u32*>(&Ah[r*GA_RS + c]);
                u32 ah1 = *reinterpret_cast<u32*>(&Ah[(r+8)*GA_RS + c]);
                u32 ah2 = *reinterpret_cast<u32*>(&Ah[r*GA_RS + c + 8]);
                u32 ah3 = *reinterpret_cast<u32*>(&Ah[(r+8)*GA_RS + c + 8]);
                u32 al0 = *reinterpret_cast<u32*>(&Al[r*GA_RS + c]);
                u32 al1 = *reinterpret_cast<u32*>(&Al[(r+8)*GA_RS + c]);
                u32 al2 = *reinterpret_cast<u32*>(&Al[r*GA_RS + c + 8]);
                u32 al3 = *reinterpret_cast<u32*>(&Al[(r+8)*GA_RS + c + 8]);
#pragma unroll
                for (int nf = 0; nf < 4; nf++) {
                    mma_bf16(acc[mf][nf], ah0,ah1,ah2,ah3, bhf[nf][0], bhf[nf][1]);
                    mma_bf16(acc[mf][nf], ah0,ah1,ah2,ah3, blf[nf][0], blf[nf][1]);
                    mma_bf16(acc[mf][nf], al0,al1,al2,al3, bhf[nf][0], bhf[nf][1]);
                }
            }
        }
        __syncthreads();
    }
#pragma unroll
    for (int mf = 0; mf < 4; mf++) {
#pragma unroll
        for (int nf = 0; nf < 4; nf++) {
            int r = bm + wm*64 + mf*16 + (lane >> 2);
            int c = bn + wn*32 + nf*8 + (lane & 3)*2;
            float b0 = bias[c], b1 = bias[c+1];
            float v0 = acc[mf][nf][0] + b0, v1 = acc[mf][nf][1] + b1;
            float v2 = acc[mf][nf][2] + b0, v3 = acc[mf][nf][3] + b1;
            if (relu) { v0=fmaxf(v0,0.f); v1=fmaxf(v1,0.f); v2=fmaxf(v2,0.f); v3=fmaxf(v3,0.f); }
            *reinterpret_cast<float2*>(&C[(size_t)r*N + c])     = make_float2(v0, v1);
            *reinterpret_cast<float2*>(&C[(size_t)(r+8)*N + c]) = make_float2(v2, v3);
        }
    }
}

// ---------------- tensor attention scores: S = scale * Q K^T ----------------
// Block 128q x 128t, hd=64 resident, 8 warps (2m x 4n), bf16-split.
#define SC_RS 72
#define SC_SMEM_T (4*128*SC_RS*2)
__global__ __launch_bounds__(256)
void attn_scores_t(const float* __restrict__ Q, const float* __restrict__ K_,
                   float* __restrict__ S, float scale)
{
    extern __shared__ u16 smem_sc[];
    u16* Qh = smem_sc;
    u16* Ql = Qh + 128*SC_RS;
    u16* Kh = Ql + 128*SC_RS;
    u16* Kl = Kh + 128*SC_RS;
    int bh = blockIdx.z;
    int b = bh / NH, h = bh - b*NH;
    int tid = threadIdx.x;
    int lane = tid & 31, wid = tid >> 5;
    int wm = wid & 1, wn = wid >> 1;
    size_t base = ((size_t)b*SEQ)*DIM + h*HD;
    int q0 = blockIdx.y*128, t0 = blockIdx.x*128;

#pragma unroll
    for (int it = 0; it < 8; it++) {
        int idx = it*256 + tid;
        int r  = idx >> 4;
        int c4 = (idx & 15) * 4;
        float4 vq = *reinterpret_cast<const float4*>(&Q[base + (size_t)(q0+r)*DIM + c4]);
        float4 vk = *reinterpret_cast<const float4*>(&K_[base + (size_t)(t0+r)*DIM + c4]);
        u16 h0,l0,h1,l1,h2,l2,h3,l3;
        bsplit(vq.x,h0,l0); bsplit(vq.y,h1,l1); bsplit(vq.z,h2,l2); bsplit(vq.w,h3,l3);
        *reinterpret_cast<u32*>(&Qh[r*SC_RS + c4])     = pk(h0,h1);
        *reinterpret_cast<u32*>(&Qh[r*SC_RS + c4 + 2]) = pk(h2,h3);
        *reinterpret_cast<u32*>(&Ql[r*SC_RS + c4])     = pk(l0,l1);
        *reinterpret_cast<u32*>(&Ql[r*SC_RS + c4 + 2]) = pk(l2,l3);
        bsplit(vk.x,h0,l0); bsplit(vk.y,h1,l1); bsplit(vk.z,h2,l2); bsplit(vk.w,h3,l3);
        *reinterpret_cast<u32*>(&Kh[r*SC_RS + c4])     = pk(h0,h1);
        *reinterpret_cast<u32*>(&Kh[r*SC_RS + c4 + 2]) = pk(h2,h3);
        *reinterpret_cast<u32*>(&Kl[r*SC_RS + c4])     = pk(l0,l1);
        *reinterpret_cast<u32*>(&Kl[r*SC_RS + c4 + 2]) = pk(l2,l3);
    }
    __syncthreads();

    float acc[4][4][4];
#pragma unroll
    for (int i=0;i<4;i++)
#pragma unroll
        for (int j=0;j<4;j++)
#pragma unroll
            for (int q=0;q<4;q++) acc[i][j][q]=0.f;

#pragma unroll
    for (int ks = 0; ks < 4; ks++) {
        int c = ks*16 + (lane & 3)*2;
        u32 bhf[4][2], blf[4][2];
#pragma unroll
        for (int nf = 0; nf < 4; nf++) {
            int n = wn*32 + nf*8 + (lane >> 2);
            bhf[nf][0] = *reinterpret_cast<u32*>(&Kh[n*SC_RS + c]);
            bhf[nf][1] = *reinterpret_cast<u32*>(&Kh[n*SC_RS + c + 8]);
            blf[nf][0] = *reinterpret_cast<u32*>(&Kl[n*SC_RS + c]);
            blf[nf][1] = *reinterpret_cast<u32*>(&Kl[n*SC_RS + c + 8]);
        }
#pragma unroll
        for (int mf = 0; mf < 4; mf++) {
            int r = wm*64 + mf*16 + (lane >> 2);
            u32 ah0 = *reinterpret_cast<u32*>(&Qh[r*SC_RS + c]);
            u32 ah1 = *reinterpret_cast<u32*>(&Qh[(r+8)*SC_RS + c]);
            u32 ah2 = *reinterpret_cast<u32*>(&Qh[r*SC_RS + c + 8]);
            u32 ah3 = *reinterpret_cast<u32*>(&Qh[(r+8)*SC_RS + c + 8]);
            u32 al0 = *reinterpret_cast<u32*>(&Ql[r*SC_RS + c]);
            u32 al1 = *reinterpret_cast<u32*>(&Ql[(r+8)*SC_RS + c]);
            u32 al2 = *reinterpret_cast<u32*>(&Ql[r*SC_RS + c + 8]);
            u32 al3 = *reinterpret_cast<u32*>(&Ql[(r+8)*SC_RS + c + 8]);
#pragma unroll
            for (int nf = 0; nf < 4; nf++) {
                mma_bf16(acc[mf][nf], ah0,ah1,ah2,ah3, bhf[nf][0], bhf[nf][1]);
                mma_bf16(acc[mf][nf], ah0,ah1,ah2,ah3, blf[nf][0], blf[nf][1]);
                mma_bf16(acc[mf][nf], al0,al1,al2,al3, bhf[nf][0], bhf[nf][1]);
            }
        }
    }

    float* Sp = S + (size_t)bh*SEQ*SEQ;
#pragma unroll
    for (int mf = 0; mf < 4; mf++) {
#pragma unroll
        for (int nf = 0; nf < 4; nf++) {
            int r = q0 + wm*64 + mf*16 + (lane >> 2);
            int c = t0 + wn*32 + nf*8 + (lane & 3)*2;
            *reinterpret_cast<float2*>(&Sp[(size_t)r*SEQ + c]) =
                make_float2(acc[mf][nf][0]*scale, acc[mf][nf][1]*scale);
            *reinterpret_cast<float2*>(&Sp[(size_t)(r+8)*SEQ + c]) =
                make_float2(acc[mf][nf][2]*scale, acc[mf][nf][3]*scale);
        }
    }
}

// ---------------- row softmax over last dim (SEQ=1024) ----------------
__global__ __launch_bounds__(256)
void softmax_rows(float* __restrict__ S)
{
    float4* row = reinterpret_cast<float4*>(S + (size_t)blockIdx.x * SEQ);
    int t = threadIdx.x;
    __shared__ float red[8];
    float4 v = row[t];
    float m = fmaxf(fmaxf(v.x, v.y), fmaxf(v.z, v.w));
#pragma unroll
    for (int o = 16; o > 0; o >>= 1) m = fmaxf(m, __shfl_xor_sync(0xffffffffu, m, o));
    if ((t & 31) == 0) red[t >> 5] = m;
    __syncthreads();
    if (t < 8) {
        float mm = red[t];
#pragma unroll
        for (int o = 4; o > 0; o >>= 1) mm = fmaxf(mm, __shfl_xor_sync(0xffu, mm, o));
        red[t] = mm;
    }
    __syncthreads();
    m = red[0];
    __syncthreads();
    v.x = fast_exp(v.x - m); v.y = fast_exp(v.y - m);
    v.z = fast_exp(v.z - m); v.w = fast_exp(v.w - m);
    float s = v.x + v.y + v.z + v.w;
#pragma unroll
    for (int o = 16; o > 0; o >>= 1) s += __shfl_xor_sync(0xffffffffu, s, o);
    if ((t & 31) == 0) red[t >> 5] = s;
    __syncthreads();
    if (t < 8) {
        float ss = red[t];
#pragma unroll
        for (int o = 4; o > 0; o >>= 1) ss += __shfl_xor_sync(0xffu, ss, o);
        red[t] = ss;
    }
    __syncthreads();
    float inv = 1.0f / red[0];
    v.x *= inv; v.y *= inv; v.z *= inv; v.w *= inv;
    row[t] = v;
}

// ---------------- tensor A @ V -> merged layout ----------------
// Block 128q x 64e, BK=32 over SEQ, 8 warps (4m x 2n), warp tile 32x32.
#define AV_A_RS 40
#define AV_V_RS 72
__global__ __launch_bounds__(256)
void attn_av_t(const float* __restrict__ A, const float* __restrict__ V,
               float* __restrict__ O)
{
    __shared__ u16 Ah[128*AV_A_RS], Al[128*AV_A_RS];
    __shared__ u16 Vh[32*AV_V_RS],  Vl[32*AV_V_RS];
    int bh = blockIdx.z;
    int b = bh / NH, h = bh - b*NH;
    int tid = threadIdx.x;
    int lane = tid & 31, wid = tid >> 5;
    int wm = wid & 3, wn = wid >> 2;
    int s0 = blockIdx.x * 128;
    const float* Ap = A + (size_t)bh*SEQ*SEQ;
    size_t vbase = ((size_t)b*SEQ)*DIM + h*HD;

    float acc[2][4][4];
#pragma unroll
    for (int i=0;i<2;i++)
#pragma unroll
        for (int j=0;j<4;j++)
#pragma unroll
            for (int q=0;q<4;q++) acc[i][j][q]=0.f;

    for (int t0 = 0; t0 < SEQ; t0 += 32) {
#pragma unroll
        for (int it = 0; it < 4; it++) {
            int idx = it*256 + tid;
            int r = idx >> 3, c4 = (idx & 7) * 4;
            float4 v = *reinterpret_cast<const float4*>(Ap + (size_t)(s0+r)*SEQ + t0 + c4);
            u16 h0,l0,h1,l1,h2,l2,h3,l3;
            bsplit(v.x,h0,l0); bsplit(v.y,h1,l1); bsplit(v.z,h2,l2); bsplit(v.w,h3,l3);
            *reinterpret_cast<u32*>(&Ah[r*AV_A_RS + c4])     = pk(h0,h1);
            *reinterpret_cast<u32*>(&Ah[r*AV_A_RS + c4 + 2]) = pk(h2,h3);
            *reinterpret_cast<u32*>(&Al[r*AV_A_RS + c4])     = pk(l0,l1);
            *reinterpret_cast<u32*>(&Al[r*AV_A_RS + c4 + 2]) = pk(l2,l3);
        }
#pragma unroll
        for (int it = 0; it < 2; it++) {
            int idx = it*256 + tid;
            int kk = idx >> 4, e4 = (idx & 15) * 4;
            float4 v = *reinterpret_cast<const float4*>(V + vbase + (size_t)(t0+kk)*DIM + e4);
            u16 h0,l0,h1,l1,h2,l2,h3,l3;
            bsplit(v.x,h0,l0); bsplit(v.y,h1,l1); bsplit(v.z,h2,l2); bsplit(v.w,h3,l3);
            *reinterpret_cast<u32*>(&Vh[kk*AV_V_RS + e4])     = pk(h0,h1);
            *reinterpret_cast<u32*>(&Vh[kk*AV_V_RS + e4 + 2]) = pk(h2,h3);
            *reinterpret_cast<u32*>(&Vl[kk*AV_V_RS + e4])     = pk(l0,l1);
            *reinterpret_cast<u32*>(&Vl[kk*AV_V_RS + e4 + 2]) = pk(l2,l3);
        }
        __syncthreads();
#pragma unroll
        for (int ks = 0; ks < 32; ks += 16) {
            u32 bhf[4][2], blf[4][2];
#pragma unroll
            for (int nf = 0; nf < 4; nf++) {
                int n  = wn*32 + nf*8 + (lane >> 2);
                int k0 = ks + (lane & 3)*2;
                bhf[nf][0] = pk(Vh[k0*AV_V_RS+n],     Vh[(k0+1)*AV_V_RS+n]);
                bhf[nf][1] = pk(Vh[(k0+8)*AV_V_RS+n], Vh[(k0+9)*AV_V_RS+n]);
                blf[nf][0] = pk(Vl[k0*AV_V_RS+n],     Vl[(k0+1)*AV_V_RS+n]);
                blf[nf][1] = pk(Vl[(k0+8)*AV_V_RS+n], Vl[(k0+9)*AV_V_RS+n]);
            }
#pragma unroll
            for (int mf = 0; mf < 2; mf++) {
                int r = wm*32 + mf*16 + (lane >> 2);
                int c = ks + (lane & 3)*2;
                u32 ah0 = *reinterpret_cast<u32*>(&Ah[r*AV_A_RS + c]);
                u32 ah1 = *reinterpret_cast<u32*>(&Ah[(r+8)*AV_A_RS + c]);
                u32 ah2 = *reinterpret_cast<u32*>(&Ah[r*AV_A_RS + c + 8]);
                u32 ah3 = *reinterpret_cast<u32*>(&Ah[(r+8)*AV_A_RS + c + 8]);
                u32 al0 = *reinterpret_cast<u32*>(&Al[r*AV_A_RS + c]);
                u32 al1 = *reinterpret_cast<u32*>(&Al[(r+8)*AV_A_RS + c]);
                u32 al2 = *reinterpret_cast<u32*>(&Al[r*AV_A_RS + c + 8]);
                u32 al3 = *reinterpret_cast<u32*>(&Al[(r+8)*AV_A_RS + c + 8]);
#pragma unroll
                for (int nf = 0; nf < 4; nf++) {
                    mma_bf16(acc[mf][nf], ah0,ah1,ah2,ah3, bhf[nf][0], bhf[nf][1]);
                    mma_bf16(acc[mf][nf], ah0,ah1,ah2,ah3, blf[nf][0], blf[nf][1]);
                    mma_bf16(acc[mf][nf], al0,al1,al2,al3, bhf[nf][0], bhf[nf][1]);
                }
            }
        }
        __syncthreads();
    }
#pragma unroll
    for (int mf = 0; mf < 2; mf++) {
#pragma unroll
        for (int nf = 0; nf < 4; nf++) {
            size_t row = (size_t)b*SEQ + s0 + wm*32 + mf*16 + (lane >> 2);
            int col = h*HD + wn*32 + nf*8 + (lane & 3)*2;
            *reinterpret_cast<float2*>(&O[row*DIM + col]) =
                make_float2(acc[mf][nf][0], acc[mf][nf][1]);
            *reinterpret_cast<float2*>(&O[(row+8)*DIM + col]) =
                make_float2(acc[mf][nf][2], acc[mf][nf][3]);
        }
    }
}

// ---------------- batch norm ----------------
__global__ void bn_zero()
{
    int t = blockIdx.x*256 + threadIdx.x;
    if (t < DIM) { g_sum[t] = 0.0; g_sum2[t] = 0.0; }
}

__global__ __launch_bounds__(256)
void bn_add_stats(const float* __restrict__ X, const float* __restrict__ Y,
                  float* __restrict__ Z)
{
    int f  = blockIdx.x*32 + threadIdx.x;
    int rb = blockIdx.y*512;
    float s = 0.0f, s2 = 0.0f;
    for (int r = rb + threadIdx.y; r < rb + 512; r += 8) {
        size_t idx = (size_t)r*DIM + f;
        float v = X[idx] + Y[idx];
        Z[idx] = v;
        s += v; s2 = fmaf(v, v, s2);
    }
    __shared__ double sh[2][8][32];
    sh[0][threadIdx.y][threadIdx.x] = (double)s;
    sh[1][threadIdx.y][threadIdx.x] = (double)s2;
    __syncthreads();
    if (threadIdx.y == 0) {
        double ts = 0.0, ts2 = 0.0;
#pragma unroll
        for (int i = 0; i < 8; i++) { ts += sh[0][i][threadIdx.x]; ts2 += sh[1][i][threadIdx.x]; }
        atomicAdd(&g_sum[f], ts);
        atomicAdd(&g_sum2[f], ts2);
    }
}

__global__ void bn_finalize(const float* __restrict__ g, const float* __restrict__ b)
{
    int f = blockIdx.x*256 + threadIdx.x;
    if (f >= DIM) return;
    double mu  = g_sum[f]  * (1.0 / ROWS);
    double var = g_sum2[f] * (1.0 / ROWS) - mu*mu;
    float rstd = (float)(1.0 / sqrt(var + 1e-5));
    float sc = g[f] * rstd;
    g_bnsc[f] = sc;
    g_bnsh[f] = b[f] - (float)mu * sc;
}

__global__ void bn_apply(const float* __restrict__ Z, float* __restrict__ O)
{
    int idx = blockIdx.x*256 + threadIdx.x;
    if (idx >= ROWS*DIM) return;
    int f = idx % DIM;
    O[idx] = fmaf(Z[idx], g_bnsc[f], g_bnsh[f]);
}

// ---------------- launch ----------------
static float* sym(const void* s)
{
    void* p = nullptr;
    cudaGetSymbolAddress(&p, s);
    return (float*)p;
}

extern "C" void kernel_launch(void* const* d_in, const int* in_sizes, int n_in,
                              void* d_out, int out_size)
{
    const int*   x     = (const int*)  d_in[0];
    const float* encod = (const float*)d_in[1];
    const float* embed = (const float*)d_in[2];
    const float* Wq  = (const float*)d_in[3];  const float* bq  = (const float*)d_in[4];
    const float* Wk  = (const float*)d_in[5];  const float* bk  = (const float*)d_in[6];
    const float* Wv  = (const float*)d_in[7];  const float* bv  = (const float*)d_in[8];
    const float* g1  = (const float*)d_in[9];  const float* b1  = (const float*)d_in[10];
    const float* Wq2 = (const float*)d_in[11]; const float* bq2 = (const float*)d_in[12];
    const float* Wk2 = (const float*)d_in[13]; const float* bk2 = (const float*)d_in[14];
    const float* Wv2 = (const float*)d_in[15]; const float* bv2 = (const float*)d_in[16];
    const float* Wo2 = (const float*)d_in[17]; const float* bo2 = (const float*)d_in[18];
    const float* g2  = (const float*)d_in[19]; const float* b2  = (const float*)d_in[20];
    const float* Wf  = (const float*)d_in[21]; const float* bf  = (const float*)d_in[22];
    float* out = (float*)d_out;

    float *im = sym(g_im), *q = sym(g_q), *k = sym(g_k), *v = sym(g_v);
    float *sa = sym(g_sa), *z = sym(g_z), *t1 = sym(g_t1), *v2 = sym(g_v2);
    float *av2 = sym(g_av2), *m2 = sym(g_m2), *t2 = sym(g_t2), *ff = sym(g_ff);
    float *q2 = sym(g_q2), *k2 = sym(g_k2), *S = sym(g_S), *A2 = sym(g_A2);

    cudaFuncSetAttribute(attn_scores_t, cudaFuncAttributeMaxDynamicSharedMemorySize, SC_SMEM_T);

    const float scale1 = 1.0f / sqrtf((float)DIM);
    const float scale2 = 1.0f / sqrtf((float)HD);

    dim3 gemmGrid(DIM/128, ROWS/128);      // (6, 32)
    dim3 scGrid(SEQ/128, SEQ/128, NBH);    // (8, 8, 48)
    dim3 avGrid(SEQ/128, 1, NBH);          // (8, 1, 48)
    dim3 bnGrid(DIM/32, 8);
    dim3 bnBlk(32, 8);
    int ewBlocks = (ROWS*DIM + 255)/256;

    embed_pos_kernel<<<ewBlocks, 256>>>(x, embed, im);

    // loop-invariant cross-attention probabilities A2 = softmax(Q2 K2^T / 8)
    gemm_bias_t<<<gemmGrid, 256>>>(encod, DIM, 0,   Wq2, bq2, q2, DIM, DIM/2, 0);
    gemm_bias_t<<<gemmGrid, 256>>>(encod, DIM, 384, Wk2, bk2, k2, DIM, DIM/2, 0);
    attn_scores_t<<<scGrid, 256, SC_SMEM_T>>>(q2, k2, A2, scale2);
    softmax_rows<<<NBH*SEQ, 256>>>(A2);

    for (int li = 0; li < NITER; li++) {
        gemm_bias_t<<<gemmGrid, 256>>>(im, DIM, 0,   Wq, bq, q, DIM, DIM/3, 1);
        gemm_bias_t<<<gemmGrid, 256>>>(im, DIM, 256, Wk, bk, k, DIM, DIM/3, 1);
        gemm_bias_t<<<gemmGrid, 256>>>(im, DIM, 512, Wv, bv, v, DIM, DIM/3, 1);
        attn_scores_t<<<scGrid, 256, SC_SMEM_T>>>(q, k, S, scale1);
        softmax_rows<<<NBH*SEQ, 256>>>(S);
        attn_av_t<<<avGrid, 256>>>(S, v, sa);

        bn_zero<<<3, 256>>>();
        bn_add_stats<<<bnGrid, bnBlk>>>(im, sa, z);
        bn_finalize<<<3, 256>>>(g1, b1);
        bn_apply<<<ewBlocks, 256>>>(z, t1);

        gemm_bias_t<<<gemmGrid, 256>>>(t1, DIM, 0, Wv2, bv2, v2, DIM, DIM, 0);
        attn_av_t<<<avGrid, 256>>>(A2, v2, av2);
        gemm_bias_t<<<gemmGrid, 256>>>(av2, DIM, 0, Wo2, bo2, m2, DIM, DIM, 0);

        bn_zero<<<3, 256>>>();
        bn_add_stats<<<bnGrid, bnBlk>>>(m2, t1, z);
        bn_finalize<<<3, 256>>>(g2, b2);
        bn_apply<<<ewBlocks, 256>>>(z, t2);

        gemm_bias_t<<<gemmGrid, 256>>>(t2, DIM, 0, Wf, bf, ff, DIM, DIM, 0);
        bn_zero<<<3, 256>>>();
        bn_add_stats<<<bnGrid, bnBlk>>>(t2, ff, z);
        bn_finalize<<<3, 256>>>(g2, b2);
        bn_apply<<<ewBlocks, 256>>>(z, im);
    }

    cudaMemcpyAsync(out, im, (size_t)ROWS*DIM*sizeof(float),
                    cudaMemcpyDeviceToDevice);
}

// round 7
// speedup vs baseline: 2.1868x; 1.1945x over previous
#include <cuda_runtime.h>
#include <cuda_bf16.h>
#include <math.h>

#define BSZ   4
#define SEQ   1024
#define DIM   768
#define NH    12
#define HD    64
#define ROWS  (BSZ*SEQ)      // 4096
#define NBH   (BSZ*NH)       // 48
#define NITER 2

typedef unsigned short u16;
typedef unsigned int   u32;

// ---------------- static scratch (no allocations allowed) ----------------
__device__ float g_im [ROWS*DIM];
__device__ float g_q  [ROWS*DIM];
__device__ float g_k  [ROWS*DIM];
__device__ float g_v  [ROWS*DIM];
__device__ float g_sa [ROWS*DIM];
__device__ float g_z  [ROWS*DIM];
__device__ float g_t1 [ROWS*DIM];
__device__ float g_v2 [ROWS*DIM];
__device__ float g_av2[ROWS*DIM];
__device__ float g_m2 [ROWS*DIM];
__device__ float g_t2 [ROWS*DIM];
__device__ float g_ff [ROWS*DIM];
__device__ float g_q2 [ROWS*DIM];
__device__ float g_k2 [ROWS*DIM];
__device__ float g_S  [(size_t)NBH*SEQ*SEQ];
__device__ float g_A2 [(size_t)NBH*SEQ*SEQ];
__device__ double g_sum [DIM];
__device__ double g_sum2[DIM];
__device__ float  g_bnsc[DIM];
__device__ float  g_bnsh[DIM];

// ---------------- helpers ----------------
__device__ __forceinline__ void bsplit(float x, u16& h, u16& l)
{
    __nv_bfloat16 bh = __float2bfloat16(x);
    h = __bfloat16_as_ushort(bh);
    l = __bfloat16_as_ushort(__float2bfloat16(x - __bfloat162float(bh)));
}
__device__ __forceinline__ u32 pk(u16 a, u16 b) { return (u32)a | ((u32)b << 16); }

__device__ __forceinline__ void mma_bf16(float d[4], u32 a0, u32 a1, u32 a2, u32 a3,
                                         u32 b0, u32 b1)
{
    asm volatile(
        "mma.sync.aligned.m16n8k16.row.col.f32.bf16.bf16.f32 "
        "{%0,%1,%2,%3}, {%4,%5,%6,%7}, {%8,%9}, {%0,%1,%2,%3};\n"
        : "+f"(d[0]), "+f"(d[1]), "+f"(d[2]), "+f"(d[3])
        : "r"(a0), "r"(a1), "r"(a2), "r"(a3), "r"(b0), "r"(b1));
}

// fast exp: pure FMA/ALU (no MUFU); x in [-87,0], rel err ~2e-6
__device__ __forceinline__ float fast_exp(float x)
{
    float t = fmaxf(x * 1.4426950408889634f, -120.0f);
    float r = t + 12582912.0f;
    float nf = r - 12582912.0f;
    float f = t - nf;
    float p = 1.3333558146e-3f;
    p = fmaf(p, f, 9.6181291077e-3f);
    p = fmaf(p, f, 5.5504108664e-2f);
    p = fmaf(p, f, 2.4022650695e-1f);
    p = fmaf(p, f, 6.9314718056e-1f);
    p = fmaf(p, f, 1.0f);
    int n = __float_as_int(r) - 0x4B400000;
    return __int_as_float(__float_as_int(p) + (n << 23));
}

// ---------------- embedding + positional encoding ----------------
__global__ void embed_pos_kernel(const int* __restrict__ x,
                                 const float* __restrict__ embed,
                                 float* __restrict__ out)
{
    int idx = blockIdx.x * 256 + threadIdx.x;
    if (idx >= ROWS*DIM) return;
    int r = idx / DIM, d = idx - r*DIM;
    int s = r & (SEQ-1);
    int tok = x[r];
    int i = d >> 1;
    float inv = exp2f((float)i * (-13.287712379549449f * 2.0f / (float)DIM));
    float ang = (float)s * inv;
    float pe = (d & 1) ? cosf(ang) : sinf(ang);
    out[idx] = 2.0f * embed[(size_t)tok * DIM + d] + pe;
}

// ---------------- tensor GEMM: C[M,N] = A[:, aoff:+K] @ W[K,N] + bias ----------------
// 128x128 block, BK=32, 8 warps (2m x 4n), warp tile 64x32, bf16-split 3-term.
#define GA_RS 40
#define GB_RS 136
__global__ __launch_bounds__(256, 2)
void gemm_bias_t(const float* __restrict__ A, int lda, int aoff,
                 const float* __restrict__ W,
                 const float* __restrict__ bias,
                 float* __restrict__ C,
                 int N, int K, int relu)
{
    __shared__ u16 Ah[128*GA_RS], Al[128*GA_RS];
    __shared__ u16 Bh[32*GB_RS],  Bl[32*GB_RS];
    int tid = threadIdx.x;
    int lane = tid & 31, wid = tid >> 5;
    int wm = wid & 1, wn = wid >> 1;
    int bm = blockIdx.y*128, bn = blockIdx.x*128;
    const float* Ab = A + (size_t)bm*lda + aoff;

    float acc[4][4][4];
#pragma unroll
    for (int i=0;i<4;i++)
#pragma unroll
        for (int j=0;j<4;j++)
#pragma unroll
            for (int q=0;q<4;q++) acc[i][j][q]=0.f;

    for (int kb = 0; kb < K; kb += 32) {
        // A tile 128x32
#pragma unroll
        for (int it = 0; it < 4; it++) {
            int idx = it*256 + tid;
            int r = idx >> 3, c4 = (idx & 7) * 4;
            float4 v = *reinterpret_cast<const float4*>(Ab + (size_t)r*lda + kb + c4);
            u16 h0,l0,h1,l1,h2,l2,h3,l3;
            bsplit(v.x,h0,l0); bsplit(v.y,h1,l1); bsplit(v.z,h2,l2); bsplit(v.w,h3,l3);
            *reinterpret_cast<u32*>(&Ah[r*GA_RS + c4])     = pk(h0,h1);
            *reinterpret_cast<u32*>(&Ah[r*GA_RS + c4 + 2]) = pk(h2,h3);
            *reinterpret_cast<u32*>(&Al[r*GA_RS + c4])     = pk(l0,l1);
            *reinterpret_cast<u32*>(&Al[r*GA_RS + c4 + 2]) = pk(l2,l3);
        }
        // B tile 32x128 (natural [k][n])
#pragma unroll
        for (int it = 0; it < 4; it++) {
            int idx = it*256 + tid;
            int kk = idx >> 5, n4 = (idx & 31) * 4;
            float4 v = *reinterpret_cast<const float4*>(W + (size_t)(kb+kk)*N + bn + n4);
            u16 h0,l0,h1,l1,h2,l2,h3,l3;
            bsplit(v.x,h0,l0); bsplit(v.y,h1,l1); bsplit(v.z,h2,l2); bsplit(v.w,h3,l3);
            *reinterpret_cast<u32*>(&Bh[kk*GB_RS + n4])     = pk(h0,h1);
            *reinterpret_cast<u32*>(&Bh[kk*GB_RS + n4 + 2]) = pk(h2,h3);
            *reinterpret_cast<u32*>(&Bl[kk*GB_RS + n4])     = pk(l0,l1);
            *reinterpret_cast<u32*>(&Bl[kk*GB_RS + n4 + 2]) = pk(l2,l3);
        }
        __syncthreads();
#pragma unroll
        for (int ks = 0; ks < 32; ks += 16) {
            u32 bhf[4][2], blf[4][2];
#pragma unroll
            for (int nf = 0; nf < 4; nf++) {
                int n  = wn*32 + nf*8 + (lane >> 2);
                int k0 = ks + (lane & 3)*2;
                bhf[nf][0] = pk(Bh[k0*GB_RS+n],     Bh[(k0+1)*GB_RS+n]);
                bhf[nf][1] = pk(Bh[(k0+8)*GB_RS+n], Bh[(k0+9)*GB_RS+n]);
                blf[nf][0] = pk(Bl[k0*GB_RS+n],     Bl[(k0+1)*GB_RS+n]);
                blf[nf][1] = pk(Bl[(k0+8)*GB_RS+n], Bl[(k0+9)*GB_RS+n]);
            }
#pragma unroll
            for (int mf = 0; mf < 4; mf++) {
                int r = wm*64 + mf*16 + (lane >> 2);
                int c = ks + (lane & 3)*2;
                u32 ah0 = *reinterpret_cast<u32*>(&Ah[r*GA_RS + c]);
                u32 ah1 = *reinterpret_cast<u32*>(&Ah[(r+8)*GA_RS + c]);
                u32 ah2 = *reinterpret_cast<u32*>(&Ah[r*GA_RS + c + 8]);
                u32 ah3 = *reinterpret_cast<u32*>(&Ah[(r+8)*GA_RS + c + 8]);
                u32 al0 = *reinterpret_cast<u32*>(&Al[r*GA_RS + c]);
                u32 al1 = *reinterpret_cast<u32*>(&Al[(r+8)*GA_RS + c]);
                u32 al2 = *reinterpret_cast<u32*>(&Al[r*GA_RS + c + 8]);
                u32 al3 = *reinterpret_cast<u32*>(&Al[(r+8)*GA_RS + c + 8]);
#pragma unroll
                for (int nf = 0; nf < 4; nf++) {
                    mma_bf16(acc[mf][nf], ah0,ah1,ah2,ah3, bhf[nf][0], bhf[nf][1]);
                    mma_bf16(acc[mf][nf], ah0,ah1,ah2,ah3, blf[nf][0], blf[nf][1]);
                    mma_bf16(acc[mf][nf], al0,al1,al2,al3, bhf[nf][0], bhf[nf][1]);
                }
            }
        }
        __syncthreads();
    }
#pragma unroll
    for (int mf = 0; mf < 4; mf++) {
#pragma unroll
        for (int nf = 0; nf < 4; nf++) {
            int r = bm + wm*64 + mf*16 + (lane >> 2);
            int c = bn + wn*32 + nf*8 + (lane & 3)*2;
            float b0 = bias[c], b1 = bias[c+1];
            float v0 = acc[mf][nf][0] + b0, v1 = acc[mf][nf][1] + b1;
            float v2 = acc[mf][nf][2] + b0, v3 = acc[mf][nf][3] + b1;
            if (relu) { v0=fmaxf(v0,0.f); v1=fmaxf(v1,0.f); v2=fmaxf(v2,0.f); v3=fmaxf(v3,0.f); }
            *reinterpret_cast<float2*>(&C[(size_t)r*N + c])     = make_float2(v0, v1);
            *reinterpret_cast<float2*>(&C[(size_t)(r+8)*N + c]) = make_float2(v2, v3);
        }
    }
}

// ---------------- tensor attention scores: S = scale * Q K^T ----------------
// Block 128q x 128t, hd=64 resident, 8 warps (2m x 4n), bf16-split.
#define SC_RS 72
#define SC_SMEM_T (4*128*SC_RS*2)
__global__ __launch_bounds__(256, 2)
void attn_scores_t(const float* __restrict__ Q, const float* __restrict__ K_,
                   float* __restrict__ S, float scale)
{
    extern __shared__ u16 smem_sc[];
    u16* Qh = smem_sc;
    u16* Ql = Qh + 128*SC_RS;
    u16* Kh = Ql + 128*SC_RS;
    u16* Kl = Kh + 128*SC_RS;
    int bh = blockIdx.z;
    int b = bh / NH, h = bh - b*NH;
    int tid = threadIdx.x;
    int lane = tid & 31, wid = tid >> 5;
    int wm = wid & 1, wn = wid >> 1;
    size_t base = ((size_t)b*SEQ)*DIM + h*HD;
    int q0 = blockIdx.y*128, t0 = blockIdx.x*128;

#pragma unroll
    for (int it = 0; it < 8; it++) {
        int idx = it*256 + tid;
        int r  = idx >> 4;
        int c4 = (idx & 15) * 4;
        float4 vq = *reinterpret_cast<const float4*>(&Q[base + (size_t)(q0+r)*DIM + c4]);
        float4 vk = *reinterpret_cast<const float4*>(&K_[base + (size_t)(t0+r)*DIM + c4]);
        u16 h0,l0,h1,l1,h2,l2,h3,l3;
        bsplit(vq.x,h0,l0); bsplit(vq.y,h1,l1); bsplit(vq.z,h2,l2); bsplit(vq.w,h3,l3);
        *reinterpret_cast<u32*>(&Qh[r*SC_RS + c4])     = pk(h0,h1);
        *reinterpret_cast<u32*>(&Qh[r*SC_RS + c4 + 2]) = pk(h2,h3);
        *reinterpret_cast<u32*>(&Ql[r*SC_RS + c4])     = pk(l0,l1);
        *reinterpret_cast<u32*>(&Ql[r*SC_RS + c4 + 2]) = pk(l2,l3);
        bsplit(vk.x,h0,l0); bsplit(vk.y,h1,l1); bsplit(vk.z,h2,l2); bsplit(vk.w,h3,l3);
        *reinterpret_cast<u32*>(&Kh[r*SC_RS + c4])     = pk(h0,h1);
        *reinterpret_cast<u32*>(&Kh[r*SC_RS + c4 + 2]) = pk(h2,h3);
        *reinterpret_cast<u32*>(&Kl[r*SC_RS + c4])     = pk(l0,l1);
        *reinterpret_cast<u32*>(&Kl[r*SC_RS + c4 + 2]) = pk(l2,l3);
    }
    __syncthreads();

    float acc[4][4][4];
#pragma unroll
    for (int i=0;i<4;i++)
#pragma unroll
        for (int j=0;j<4;j++)
#pragma unroll
            for (int q=0;q<4;q++) acc[i][j][q]=0.f;

#pragma unroll
    for (int ks = 0; ks < 4; ks++) {
        int c = ks*16 + (lane & 3)*2;
        u32 bhf[4][2], blf[4][2];
#pragma unroll
        for (int nf = 0; nf < 4; nf++) {
            int n = wn*32 + nf*8 + (lane >> 2);
            bhf[nf][0] = *reinterpret_cast<u32*>(&Kh[n*SC_RS + c]);
            bhf[nf][1] = *reinterpret_cast<u32*>(&Kh[n*SC_RS + c + 8]);
            blf[nf][0] = *reinterpret_cast<u32*>(&Kl[n*SC_RS + c]);
            blf[nf][1] = *reinterpret_cast<u32*>(&Kl[n*SC_RS + c + 8]);
        }
#pragma unroll
        for (int mf = 0; mf < 4; mf++) {
            int r = wm*64 + mf*16 + (lane >> 2);
            u32 ah0 = *reinterpret_cast<u32*>(&Qh[r*SC_RS + c]);
            u32 ah1 = *reinterpret_cast<u32*>(&Qh[(r+8)*SC_RS + c]);
            u32 ah2 = *reinterpret_cast<u32*>(&Qh[r*SC_RS + c + 8]);
            u32 ah3 = *reinterpret_cast<u32*>(&Qh[(r+8)*SC_RS + c + 8]);
            u32 al0 = *reinterpret_cast<u32*>(&Ql[r*SC_RS + c]);
            u32 al1 = *reinterpret_cast<u32*>(&Ql[(r+8)*SC_RS + c]);
            u32 al2 = *reinterpret_cast<u32*>(&Ql[r*SC_RS + c + 8]);
            u32 al3 = *reinterpret_cast<u32*>(&Ql[(r+8)*SC_RS + c + 8]);
#pragma unroll
            for (int nf = 0; nf < 4; nf++) {
                mma_bf16(acc[mf][nf], ah0,ah1,ah2,ah3, bhf[nf][0], bhf[nf][1]);
                mma_bf16(acc[mf][nf], ah0,ah1,ah2,ah3, blf[nf][0], blf[nf][1]);
                mma_bf16(acc[mf][nf], al0,al1,al2,al3, bhf[nf][0], bhf[nf][1]);
            }
        }
    }

    float* Sp = S + (size_t)bh*SEQ*SEQ;
#pragma unroll
    for (int mf = 0; mf < 4; mf++) {
#pragma unroll
        for (int nf = 0; nf < 4; nf++) {
            int r = q0 + wm*64 + mf*16 + (lane >> 2);
            int c = t0 + wn*32 + nf*8 + (lane & 3)*2;
            *reinterpret_cast<float2*>(&Sp[(size_t)r*SEQ + c]) =
                make_float2(acc[mf][nf][0]*scale, acc[mf][nf][1]*scale);
            *reinterpret_cast<float2*>(&Sp[(size_t)(r+8)*SEQ + c]) =
                make_float2(acc[mf][nf][2]*scale, acc[mf][nf][3]*scale);
        }
    }
}

// ---------------- row softmax over last dim (SEQ=1024) ----------------
__global__ __launch_bounds__(256)
void softmax_rows(float* __restrict__ S)
{
    float4* row = reinterpret_cast<float4*>(S + (size_t)blockIdx.x * SEQ);
    int t = threadIdx.x;
    __shared__ float red[8];
    float4 v = row[t];
    float m = fmaxf(fmaxf(v.x, v.y), fmaxf(v.z, v.w));
#pragma unroll
    for (int o = 16; o > 0; o >>= 1) m = fmaxf(m, __shfl_xor_sync(0xffffffffu, m, o));
    if ((t & 31) == 0) red[t >> 5] = m;
    __syncthreads();
    if (t < 8) {
        float mm = red[t];
#pragma unroll
        for (int o = 4; o > 0; o >>= 1) mm = fmaxf(mm, __shfl_xor_sync(0xffu, mm, o));
        red[t] = mm;
    }
    __syncthreads();
    m = red[0];
    __syncthreads();
    v.x = fast_exp(v.x - m); v.y = fast_exp(v.y - m);
    v.z = fast_exp(v.z - m); v.w = fast_exp(v.w - m);
    float s = v.x + v.y + v.z + v.w;
#pragma unroll
    for (int o = 16; o > 0; o >>= 1) s += __shfl_xor_sync(0xffffffffu, s, o);
    if ((t & 31) == 0) red[t >> 5] = s;
    __syncthreads();
    if (t < 8) {
        float ss = red[t];
#pragma unroll
        for (int o = 4; o > 0; o >>= 1) ss += __shfl_xor_sync(0xffu, ss, o);
        red[t] = ss;
    }
    __syncthreads();
    float inv = 1.0f / red[0];
    v.x *= inv; v.y *= inv; v.z *= inv; v.w *= inv;
    row[t] = v;
}

// ---------------- tensor A @ V -> merged layout ----------------
// Block 128q x 64e, BK=32 over SEQ, 8 warps (4m x 2n), warp tile 32x32.
#define AV_A_RS 40
#define AV_V_RS 72
__global__ __launch_bounds__(256, 2)
void attn_av_t(const float* __restrict__ A, const float* __restrict__ V,
               float* __restrict__ O)
{
    __shared__ u16 Ah[128*AV_A_RS], Al[128*AV_A_RS];
    __shared__ u16 Vh[32*AV_V_RS],  Vl[32*AV_V_RS];
    int bh = blockIdx.z;
    int b = bh / NH, h = bh - b*NH;
    int tid = threadIdx.x;
    int lane = tid & 31, wid = tid >> 5;
    int wm = wid & 3, wn = wid >> 2;
    int s0 = blockIdx.x * 128;
    const float* Ap = A + (size_t)bh*SEQ*SEQ;
    size_t vbase = ((size_t)b*SEQ)*DIM + h*HD;

    float acc[2][4][4];
#pragma unroll
    for (int i=0;i<2;i++)
#pragma unroll
        for (int j=0;j<4;j++)
#pragma unroll
            for (int q=0;q<4;q++) acc[i][j][q]=0.f;

    for (int t0 = 0; t0 < SEQ; t0 += 32) {
#pragma unroll
        for (int it = 0; it < 4; it++) {
            int idx = it*256 + tid;
            int r = idx >> 3, c4 = (idx & 7) * 4;
            float4 v = *reinterpret_cast<const float4*>(Ap + (size_t)(s0+r)*SEQ + t0 + c4);
            u16 h0,l0,h1,l1,h2,l2,h3,l3;
            bsplit(v.x,h0,l0); bsplit(v.y,h1,l1); bsplit(v.z,h2,l2); bsplit(v.w,h3,l3);
            *reinterpret_cast<u32*>(&Ah[r*AV_A_RS + c4])     = pk(h0,h1);
            *reinterpret_cast<u32*>(&Ah[r*AV_A_RS + c4 + 2]) = pk(h2,h3);
            *reinterpret_cast<u32*>(&Al[r*AV_A_RS + c4])     = pk(l0,l1);
            *reinterpret_cast<u32*>(&Al[r*AV_A_RS + c4 + 2]) = pk(l2,l3);
        }
#pragma unroll
        for (int it = 0; it < 2; it++) {
            int idx = it*256 + tid;
            int kk = idx >> 4, e4 = (idx & 15) * 4;
            float4 v = *reinterpret_cast<const float4*>(V + vbase + (size_t)(t0+kk)*DIM + e4);
            u16 h0,l0,h1,l1,h2,l2,h3,l3;
            bsplit(v.x,h0,l0); bsplit(v.y,h1,l1); bsplit(v.z,h2,l2); bsplit(v.w,h3,l3);
            *reinterpret_cast<u32*>(&Vh[kk*AV_V_RS + e4])     = pk(h0,h1);
            *reinterpret_cast<u32*>(&Vh[kk*AV_V_RS + e4 + 2]) = pk(h2,h3);
            *reinterpret_cast<u32*>(&Vl[kk*AV_V_RS + e4])     = pk(l0,l1);
            *reinterpret_cast<u32*>(&Vl[kk*AV_V_RS + e4 + 2]) = pk(l2,l3);
        }
        __syncthreads();
#pragma unroll
        for (int ks = 0; ks < 32; ks += 16) {
            u32 bhf[4][2], blf[4][2];
#pragma unroll
            for (int nf = 0; nf < 4; nf++) {
                int n  = wn*32 + nf*8 + (lane >> 2);
                int k0 = ks + (lane & 3)*2;
                bhf[nf][0] = pk(Vh[k0*AV_V_RS+n],     Vh[(k0+1)*AV_V_RS+n]);
                bhf[nf][1] = pk(Vh[(k0+8)*AV_V_RS+n], Vh[(k0+9)*AV_V_RS+n]);
                blf[nf][0] = pk(Vl[k0*AV_V_RS+n],     Vl[(k0+1)*AV_V_RS+n]);
                blf[nf][1] = pk(Vl[(k0+8)*AV_V_RS+n], Vl[(k0+9)*AV_V_RS+n]);
            }
#pragma unroll
            for (int mf = 0; mf < 2; mf++) {
                int r = wm*32 + mf*16 + (lane >> 2);
                int c = ks + (lane & 3)*2;
                u32 ah0 = *reinterpret_cast<u32*>(&Ah[r*AV_A_RS + c]);
                u32 ah1 = *reinterpret_cast<u32*>(&Ah[(r+8)*AV_A_RS + c]);
                u32 ah2 = *reinterpret_cast<u32*>(&Ah[r*AV_A_RS + c + 8]);
                u32 ah3 = *reinterpret_cast<u32*>(&Ah[(r+8)*AV_A_RS + c + 8]);
                u32 al0 = *reinterpret_cast<u32*>(&Al[r*AV_A_RS + c]);
                u32 al1 = *reinterpret_cast<u32*>(&Al[(r+8)*AV_A_RS + c]);
                u32 al2 = *reinterpret_cast<u32*>(&Al[r*AV_A_RS + c + 8]);
                u32 al3 = *reinterpret_cast<u32*>(&Al[(r+8)*AV_A_RS + c + 8]);
#pragma unroll
                for (int nf = 0; nf < 4; nf++) {
                    mma_bf16(acc[mf][nf], ah0,ah1,ah2,ah3, bhf[nf][0], bhf[nf][1]);
                    mma_bf16(acc[mf][nf], ah0,ah1,ah2,ah3, blf[nf][0], blf[nf][1]);
                    mma_bf16(acc[mf][nf], al0,al1,al2,al3, bhf[nf][0], bhf[nf][1]);
                }
            }
        }
        __syncthreads();
    }
#pragma unroll
    for (int mf = 0; mf < 2; mf++) {
#pragma unroll
        for (int nf = 0; nf < 4; nf++) {
            size_t row = (size_t)b*SEQ + s0 + wm*32 + mf*16 + (lane >> 2);
            int col = h*HD + wn*32 + nf*8 + (lane & 3)*2;
            *reinterpret_cast<float2*>(&O[row*DIM + col]) =
                make_float2(acc[mf][nf][0], acc[mf][nf][1]);
            *reinterpret_cast<float2*>(&O[(row+8)*DIM + col]) =
                make_float2(acc[mf][nf][2], acc[mf][nf][3]);
        }
    }
}

// ---------------- batch norm ----------------
__global__ void bn_zero()
{
    int t = blockIdx.x*256 + threadIdx.x;
    if (t < DIM) { g_sum[t] = 0.0; g_sum2[t] = 0.0; }
}

__global__ __launch_bounds__(256)
void bn_add_stats(const float* __restrict__ X, const float* __restrict__ Y,
                  float* __restrict__ Z)
{
    int f  = blockIdx.x*32 + threadIdx.x;
    int rb = blockIdx.y*512;
    float s = 0.0f, s2 = 0.0f;
    for (int r = rb + threadIdx.y; r < rb + 512; r += 8) {
        size_t idx = (size_t)r*DIM + f;
        float v = X[idx] + Y[idx];
        Z[idx] = v;
        s += v; s2 = fmaf(v, v, s2);
    }
    __shared__ double sh[2][8][32];
    sh[0][threadIdx.y][threadIdx.x] = (double)s;
    sh[1][threadIdx.y][threadIdx.x] = (double)s2;
    __syncthreads();
    if (threadIdx.y == 0) {
        double ts = 0.0, ts2 = 0.0;
#pragma unroll
        for (int i = 0; i < 8; i++) { ts += sh[0][i][threadIdx.x]; ts2 += sh[1][i][threadIdx.x]; }
        atomicAdd(&g_sum[f], ts);
        atomicAdd(&g_sum2[f], ts2);
    }
}

__global__ void bn_finalize(const float* __restrict__ g, const float* __restrict__ b)
{
    int f = blockIdx.x*256 + threadIdx.x;
    if (f >= DIM) return;
    double mu  = g_sum[f]  * (1.0 / ROWS);
    double var = g_sum2[f] * (1.0 / ROWS) - mu*mu;
    float rstd = (float)(1.0 / sqrt(var + 1e-5));
    float sc = g[f] * rstd;
    g_bnsc[f] = sc;
    g_bnsh[f] = b[f] - (float)mu * sc;
}

__global__ void bn_apply(const float* __restrict__ Z, float* __restrict__ O)
{
    int idx = blockIdx.x*256 + threadIdx.x;
    if (idx >= ROWS*DIM) return;
    int f = idx % DIM;
    O[idx] = fmaf(Z[idx], g_bnsc[f], g_bnsh[f]);
}

// ---------------- launch ----------------
static float* sym(const void* s)
{
    void* p = nullptr;
    cudaGetSymbolAddress(&p, s);
    return (float*)p;
}

extern "C" void kernel_launch(void* const* d_in, const int* in_sizes, int n_in,
                              void* d_out, int out_size)
{
    const int*   x     = (const int*)  d_in[0];
    const float* encod = (const float*)d_in[1];
    const float* embed = (const float*)d_in[2];
    const float* Wq  = (const float*)d_in[3];  const float* bq  = (const float*)d_in[4];
    const float* Wk  = (const float*)d_in[5];  const float* bk  = (const float*)d_in[6];
    const float* Wv  = (const float*)d_in[7];  const float* bv  = (const float*)d_in[8];
    const float* g1  = (const float*)d_in[9];  const float* b1  = (const float*)d_in[10];
    const float* Wq2 = (const float*)d_in[11]; const float* bq2 = (const float*)d_in[12];
    const float* Wk2 = (const float*)d_in[13]; const float* bk2 = (const float*)d_in[14];
    const float* Wv2 = (const float*)d_in[15]; const float* bv2 = (const float*)d_in[16];
    const float* Wo2 = (const float*)d_in[17]; const float* bo2 = (const float*)d_in[18];
    const float* g2  = (const float*)d_in[19]; const float* b2  = (const float*)d_in[20];
    const float* Wf  = (const float*)d_in[21]; const float* bf  = (const float*)d_in[22];
    float* out = (float*)d_out;

    float *im = sym(g_im), *q = sym(g_q), *k = sym(g_k), *v = sym(g_v);
    float *sa = sym(g_sa), *z = sym(g_z), *t1 = sym(g_t1), *v2 = sym(g_v2);
    float *av2 = sym(g_av2), *m2 = sym(g_m2), *t2 = sym(g_t2), *ff = sym(g_ff);
    float *q2 = sym(g_q2), *k2 = sym(g_k2), *S = sym(g_S), *A2 = sym(g_A2);

    cudaFuncSetAttribute(attn_scores_t, cudaFuncAttributeMaxDynamicSharedMemorySize, SC_SMEM_T);

    const float scale1 = 1.0f / sqrtf((float)DIM);
    const float scale2 = 1.0f / sqrtf((float)HD);

    dim3 gemmGrid(DIM/128, ROWS/128);      // (6, 32)
    dim3 scGrid(SEQ/128, SEQ/128, NBH);    // (8, 8, 48)
    dim3 avGrid(SEQ/128, 1, NBH);          // (8, 1, 48)
    dim3 bnGrid(DIM/32, 8);
    dim3 bnBlk(32, 8);
    int ewBlocks = (ROWS*DIM + 255)/256;

    embed_pos_kernel<<<ewBlocks, 256>>>(x, embed, im);

    // loop-invariant cross-attention probabilities A2 = softmax(Q2 K2^T / 8)
    gemm_bias_t<<<gemmGrid, 256>>>(encod, DIM, 0,   Wq2, bq2, q2, DIM, DIM/2, 0);
    gemm_bias_t<<<gemmGrid, 256>>>(encod, DIM, 384, Wk2, bk2, k2, DIM, DIM/2, 0);
    attn_scores_t<<<scGrid, 256, SC_SMEM_T>>>(q2, k2, A2, scale2);
    softmax_rows<<<NBH*SEQ, 256>>>(A2);

    for (int li = 0; li < NITER; li++) {
        gemm_bias_t<<<gemmGrid, 256>>>(im, DIM, 0,   Wq, bq, q, DIM, DIM/3, 1);
        gemm_bias_t<<<gemmGrid, 256>>>(im, DIM, 256, Wk, bk, k, DIM, DIM/3, 1);
        gemm_bias_t<<<gemmGrid, 256>>>(im, DIM, 512, Wv, bv, v, DIM, DIM/3, 1);
        attn_scores_t<<<scGrid, 256, SC_SMEM_T>>>(q, k, S, scale1);
        softmax_rows<<<NBH*SEQ, 256>>>(S);
        attn_av_t<<<avGrid, 256>>>(S, v, sa);

        bn_zero<<<3, 256>>>();
        bn_add_stats<<<bnGrid, bnBlk>>>(im, sa, z);
        bn_finalize<<<3, 256>>>(g1, b1);
        bn_apply<<<ewBlocks, 256>>>(z, t1);

        gemm_bias_t<<<gemmGrid, 256>>>(t1, DIM, 0, Wv2, bv2, v2, DIM, DIM, 0);
        attn_av_t<<<avGrid, 256>>>(A2, v2, av2);
        gemm_bias_t<<<gemmGrid, 256>>>(av2, DIM, 0, Wo2, bo2, m2, DIM, DIM, 0);

        bn_zero<<<3, 256>>>();
        bn_add_stats<<<bnGrid, bnBlk>>>(m2, t1, z);
        bn_finalize<<<3, 256>>>(g2, b2);
        bn_apply<<<ewBlocks, 256>>>(z, t2);

        gemm_bias_t<<<gemmGrid, 256>>>(t2, DIM, 0, Wf, bf, ff, DIM, DIM, 0);
        bn_zero<<<3, 256>>>();
        bn_add_stats<<<bnGrid, bnBlk>>>(t2, ff, z);
        bn_finalize<<<3, 256>>>(g2, b2);
        bn_apply<<<ewBlocks, 256>>>(z, im);
    }

    cudaMemcpyAsync(out, im, (size_t)ROWS*DIM*sizeof(float),
                    cudaMemcpyDeviceToDevice);
}

// round 8
// speedup vs baseline: 2.8265x; 1.2925x over previous
#include <cuda_runtime.h>
#include <cuda_bf16.h>
#include <cuda_fp16.h>
#include <math.h>

#define BSZ   4
#define SEQ   1024
#define DIM   768
#define NH    12
#define HD    64
#define ROWS  (BSZ*SEQ)      // 4096
#define NBH   (BSZ*NH)       // 48
#define NITER 2

typedef unsigned short u16;
typedef unsigned int   u32;

// ---------------- static scratch (no allocations allowed) ----------------
__device__ float g_im [ROWS*DIM];
__device__ float g_q  [ROWS*DIM];
__device__ float g_k  [ROWS*DIM];
__device__ float g_v  [ROWS*DIM];
__device__ float g_sa [ROWS*DIM];
__device__ float g_z  [ROWS*DIM];
__device__ float g_t1 [ROWS*DIM];
__device__ float g_v2 [ROWS*DIM];
__device__ float g_av2[ROWS*DIM];
__device__ float g_m2 [ROWS*DIM];
__device__ float g_t2 [ROWS*DIM];
__device__ float g_ff [ROWS*DIM];
__device__ float g_q2 [ROWS*DIM];
__device__ float g_k2 [ROWS*DIM];
__device__ double g_sum [DIM];
__device__ double g_sum2[DIM];
__device__ float  g_bnsc[DIM];
__device__ float  g_bnsh[DIM];

// ---------------- helpers ----------------
__device__ __forceinline__ void bsplit(float x, u16& h, u16& l)
{
    __nv_bfloat16 bh = __float2bfloat16(x);
    h = __bfloat16_as_ushort(bh);
    l = __bfloat16_as_ushort(__float2bfloat16(x - __bfloat162float(bh)));
}
__device__ __forceinline__ void hsplit(float x, u16& h, u16& l)
{
    __half hh = __float2half_rn(x);
    h = __half_as_ushort(hh);
    l = __half_as_ushort(__float2half_rn(x - __half2float(hh)));
}
__device__ __forceinline__ u32 pk(u16 a, u16 b) { return (u32)a | ((u32)b << 16); }

__device__ __forceinline__ void mma_bf16(float d[4], u32 a0, u32 a1, u32 a2, u32 a3,
                                         u32 b0, u32 b1)
{
    asm volatile(
        "mma.sync.aligned.m16n8k16.row.col.f32.bf16.bf16.f32 "
        "{%0,%1,%2,%3}, {%4,%5,%6,%7}, {%8,%9}, {%0,%1,%2,%3};\n"
        : "+f"(d[0]), "+f"(d[1]), "+f"(d[2]), "+f"(d[3])
        : "r"(a0), "r"(a1), "r"(a2), "r"(a3), "r"(b0), "r"(b1));
}
__device__ __forceinline__ void mma_f16(float d[4], u32 a0, u32 a1, u32 a2, u32 a3,
                                        u32 b0, u32 b1)
{
    asm volatile(
        "mma.sync.aligned.m16n8k16.row.col.f32.f16.f16.f32 "
        "{%0,%1,%2,%3}, {%4,%5,%6,%7}, {%8,%9}, {%0,%1,%2,%3};\n"
        : "+f"(d[0]), "+f"(d[1]), "+f"(d[2]), "+f"(d[3])
        : "r"(a0), "r"(a1), "r"(a2), "r"(a3), "r"(b0), "r"(b1));
}

// fast exp: pure FMA/ALU (no MUFU); x <= 0, rel err ~2e-6
__device__ __forceinline__ float fast_exp(float x)
{
    float t = fmaxf(x * 1.4426950408889634f, -120.0f);
    float r = t + 12582912.0f;
    float nf = r - 12582912.0f;
    float f = t - nf;
    float p = 1.3333558146e-3f;
    p = fmaf(p, f, 9.6181291077e-3f);
    p = fmaf(p, f, 5.5504108664e-2f);
    p = fmaf(p, f, 2.4022650695e-1f);
    p = fmaf(p, f, 6.9314718056e-1f);
    p = fmaf(p, f, 1.0f);
    int n = __float_as_int(r) - 0x4B400000;
    return __int_as_float(__float_as_int(p) + (n << 23));
}

// ---------------- embedding + positional encoding ----------------
__global__ void embed_pos_kernel(const int* __restrict__ x,
                                 const float* __restrict__ embed,
                                 float* __restrict__ out)
{
    int idx = blockIdx.x * 256 + threadIdx.x;
    if (idx >= ROWS*DIM) return;
    int r = idx / DIM, d = idx - r*DIM;
    int s = r & (SEQ-1);
    int tok = x[r];
    int i = d >> 1;
    float inv = exp2f((float)i * (-13.287712379549449f * 2.0f / (float)DIM));
    float ang = (float)s * inv;
    float pe = (d & 1) ? cosf(ang) : sinf(ang);
    out[idx] = 2.0f * embed[(size_t)tok * DIM + d] + pe;
}

// ---------------- tensor GEMM: C[M,N] = A[:, aoff:+K] @ W[K,N] + bias ----------------
#define GA_RS 40
#define GB_RS 136
__global__ __launch_bounds__(256, 2)
void gemm_bias_t(const float* __restrict__ A, int lda, int aoff,
                 const float* __restrict__ W,
                 const float* __restrict__ bias,
                 float* __restrict__ C,
                 int N, int K, int relu)
{
    __shared__ u16 Ah[128*GA_RS], Al[128*GA_RS];
    __shared__ u16 Bh[32*GB_RS],  Bl[32*GB_RS];
    int tid = threadIdx.x;
    int lane = tid & 31, wid = tid >> 5;
    int wm = wid & 1, wn = wid >> 1;
    int bm = blockIdx.y*128, bn = blockIdx.x*128;
    const float* Ab = A + (size_t)bm*lda + aoff;

    float acc[4][4][4];
#pragma unroll
    for (int i=0;i<4;i++)
#pragma unroll
        for (int j=0;j<4;j++)
#pragma unroll
            for (int q=0;q<4;q++) acc[i][j][q]=0.f;

    for (int kb = 0; kb < K; kb += 32) {
#pragma unroll
        for (int it = 0; it < 4; it++) {
            int idx = it*256 + tid;
            int r = idx >> 3, c4 = (idx & 7) * 4;
            float4 v = *reinterpret_cast<const float4*>(Ab + (size_t)r*lda + kb + c4);
            u16 h0,l0,h1,l1,h2,l2,h3,l3;
            bsplit(v.x,h0,l0); bsplit(v.y,h1,l1); bsplit(v.z,h2,l2); bsplit(v.w,h3,l3);
            *reinterpret_cast<u32*>(&Ah[r*GA_RS + c4])     = pk(h0,h1);
            *reinterpret_cast<u32*>(&Ah[r*GA_RS + c4 + 2]) = pk(h2,h3);
            *reinterpret_cast<u32*>(&Al[r*GA_RS + c4])     = pk(l0,l1);
            *reinterpret_cast<u32*>(&Al[r*GA_RS + c4 + 2]) = pk(l2,l3);
        }
#pragma unroll
        for (int it = 0; it < 4; it++) {
            int idx = it*256 + tid;
            int kk = idx >> 5, n4 = (idx & 31) * 4;
            float4 v = *reinterpret_cast<const float4*>(W + (size_t)(kb+kk)*N + bn + n4);
            u16 h0,l0,h1,l1,h2,l2,h3,l3;
            bsplit(v.x,h0,l0); bsplit(v.y,h1,l1); bsplit(v.z,h2,l2); bsplit(v.w,h3,l3);
            *reinterpret_cast<u32*>(&Bh[kk*GB_RS + n4])     = pk(h0,h1);
            *reinterpret_cast<u32*>(&Bh[kk*GB_RS + n4 + 2]) = pk(h2,h3);
            *reinterpret_cast<u32*>(&Bl[kk*GB_RS + n4])     = pk(l0,l1);
            *reinterpret_cast<u32*>(&Bl[kk*GB_RS + n4 + 2]) = pk(l2,l3);
        }
        __syncthreads();
#pragma unroll
        for (int ks = 0; ks < 32; ks += 16) {
            u32 bhf[4][2], blf[4][2];
#pragma unroll
            for (int nf = 0; nf < 4; nf++) {
                int n  = wn*32 + nf*8 + (lane >> 2);
                int k0 = ks + (lane & 3)*2;
                bhf[nf][0] = pk(Bh[k0*GB_RS+n],     Bh[(k0+1)*GB_RS+n]);
                bhf[nf][1] = pk(Bh[(k0+8)*GB_RS+n], Bh[(k0+9)*GB_RS+n]);
                blf[nf][0] = pk(Bl[k0*GB_RS+n],     Bl[(k0+1)*GB_RS+n]);
                blf[nf][1] = pk(Bl[(k0+8)*GB_RS+n], Bl[(k0+9)*GB_RS+n]);
            }
#pragma unroll
            for (int mf = 0; mf < 4; mf++) {
                int r = wm*64 + mf*16 + (lane >> 2);
                int c = ks + (lane & 3)*2;
                u32 ah0 = *reinterpret_cast<u32*>(&Ah[r*GA_RS + c]);
                u32 ah1 = *reinterpret_cast<u32*>(&Ah[(r+8)*GA_RS + c]);
                u32 ah2 = *reinterpret_cast<u32*>(&Ah[r*GA_RS + c + 8]);
                u32 ah3 = *reinterpret_cast<u32*>(&Ah[(r+8)*GA_RS + c + 8]);
                u32 al0 = *reinterpret_cast<u32*>(&Al[r*GA_RS + c]);
                u32 al1 = *reinterpret_cast<u32*>(&Al[(r+8)*GA_RS + c]);
                u32 al2 = *reinterpret_cast<u32*>(&Al[r*GA_RS + c + 8]);
                u32 al3 = *reinterpret_cast<u32*>(&Al[(r+8)*GA_RS + c + 8]);
#pragma unroll
                for (int nf = 0; nf < 4; nf++) {
                    mma_bf16(acc[mf][nf], ah0,ah1,ah2,ah3, bhf[nf][0], bhf[nf][1]);
                    mma_bf16(acc[mf][nf], ah0,ah1,ah2,ah3, blf[nf][0], blf[nf][1]);
                    mma_bf16(acc[mf][nf], al0,al1,al2,al3, bhf[nf][0], bhf[nf][1]);
                }
            }
        }
        __syncthreads();
    }
#pragma unroll
    for (int mf = 0; mf < 4; mf++) {
#pragma unroll
        for (int nf = 0; nf < 4; nf++) {
            int r = bm + wm*64 + mf*16 + (lane >> 2);
            int c = bn + wn*32 + nf*8 + (lane & 3)*2;
            float b0 = bias[c], b1 = bias[c+1];
            float v0 = acc[mf][nf][0] + b0, v1 = acc[mf][nf][1] + b1;
            float v2 = acc[mf][nf][2] + b0, v3 = acc[mf][nf][3] + b1;
            if (relu) { v0=fmaxf(v0,0.f); v1=fmaxf(v1,0.f); v2=fmaxf(v2,0.f); v3=fmaxf(v3,0.f); }
            *reinterpret_cast<float2*>(&C[(size_t)r*N + c])     = make_float2(v0, v1);
            *reinterpret_cast<float2*>(&C[(size_t)(r+8)*N + c]) = make_float2(v2, v3);
        }
    }
}

// ---------------- fused flash attention: O = softmax(scale*Q K^T) V ----------------
// Grid (SEQ/128, 1, NBH), 256 thr (8 warps, 16 q-rows each).
// Q tile 128x64 resident (pre-scaled, bf16 split). K/V streamed 64 rows/iter.
// S in regs; P->fp16 frags feed PV mma directly (QK C-frag == PV A-frag layout).
#define FA_RS 72
#define FA_SMEM ((2*128*FA_RS + 4*64*FA_RS) * 2)   // 73728 bytes
__global__ __launch_bounds__(256, 2)
void fused_attn(const float* __restrict__ Q, const float* __restrict__ K_,
                const float* __restrict__ V_, float* __restrict__ O, float scale)
{
    extern __shared__ u16 sm[];
    u16* Qh = sm;
    u16* Ql = Qh + 128*FA_RS;
    u16* Kh = Ql + 128*FA_RS;
    u16* Kl = Kh + 64*FA_RS;
    u16* Vh = Kl + 64*FA_RS;
    u16* Vl = Vh + 64*FA_RS;

    int bh = blockIdx.z;
    int b = bh / NH, h = bh - b*NH;
    int tid = threadIdx.x, lane = tid & 31, w = tid >> 5;
    size_t base = ((size_t)b*SEQ)*DIM + h*HD;
    int q0 = blockIdx.x * 128;

    // Q tile (scaled): 128x64 = 2048 float4
#pragma unroll
    for (int it = 0; it < 8; it++) {
        int idx = it*256 + tid;
        int r = idx >> 4, c4 = (idx & 15) * 4;
        float4 v = *reinterpret_cast<const float4*>(&Q[base + (size_t)(q0+r)*DIM + c4]);
        v.x *= scale; v.y *= scale; v.z *= scale; v.w *= scale;
        u16 h0,l0,h1,l1,h2,l2,h3,l3;
        bsplit(v.x,h0,l0); bsplit(v.y,h1,l1); bsplit(v.z,h2,l2); bsplit(v.w,h3,l3);
        *reinterpret_cast<u32*>(&Qh[r*FA_RS + c4])     = pk(h0,h1);
        *reinterpret_cast<u32*>(&Qh[r*FA_RS + c4 + 2]) = pk(h2,h3);
        *reinterpret_cast<u32*>(&Ql[r*FA_RS + c4])     = pk(l0,l1);
        *reinterpret_cast<u32*>(&Ql[r*FA_RS + c4 + 2]) = pk(l2,l3);
    }

    float o[8][4];
#pragma unroll
    for (int i=0;i<8;i++)
#pragma unroll
        for (int j=0;j<4;j++) o[i][j]=0.f;
    float m_lo = -1e30f, m_hi = -1e30f, l_lo = 0.f, l_hi = 0.f;

    int rq = w*16 + (lane >> 2);   // q-row (within tile) for d0/d1; +8 for d2/d3

    for (int t0 = 0; t0 < SEQ; t0 += 64) {
        __syncthreads();   // prior iter's smem reads done (also covers Q store on iter 0)
        // K/V tiles 64x64: 1024 float4 each -> 4 per thread each
#pragma unroll
        for (int it = 0; it < 4; it++) {
            int idx = it*256 + tid;
            int r = idx >> 4, c4 = (idx & 15) * 4;
            float4 kv = *reinterpret_cast<const float4*>(&K_[base + (size_t)(t0+r)*DIM + c4]);
            u16 h0,l0,h1,l1,h2,l2,h3,l3;
            bsplit(kv.x,h0,l0); bsplit(kv.y,h1,l1); bsplit(kv.z,h2,l2); bsplit(kv.w,h3,l3);
            *reinterpret_cast<u32*>(&Kh[r*FA_RS + c4])     = pk(h0,h1);
            *reinterpret_cast<u32*>(&Kh[r*FA_RS + c4 + 2]) = pk(h2,h3);
            *reinterpret_cast<u32*>(&Kl[r*FA_RS + c4])     = pk(l0,l1);
            *reinterpret_cast<u32*>(&Kl[r*FA_RS + c4 + 2]) = pk(l2,l3);
            float4 vv = *reinterpret_cast<const float4*>(&V_[base + (size_t)(t0+r)*DIM + c4]);
            hsplit(vv.x,h0,l0); hsplit(vv.y,h1,l1); hsplit(vv.z,h2,l2); hsplit(vv.w,h3,l3);
            *reinterpret_cast<u32*>(&Vh[r*FA_RS + c4])     = pk(h0,h1);
            *reinterpret_cast<u32*>(&Vh[r*FA_RS + c4 + 2]) = pk(h2,h3);
            *reinterpret_cast<u32*>(&Vl[r*FA_RS + c4])     = pk(l0,l1);
            *reinterpret_cast<u32*>(&Vl[r*FA_RS + c4 + 2]) = pk(l2,l3);
        }
        __syncthreads();

        // ---- S = Q K^T (16 x 64 per warp), bf16 3-term split ----
        float sacc[8][4];
#pragma unroll
        for (int i=0;i<8;i++)
#pragma unroll
            for (int j=0;j<4;j++) sacc[i][j]=0.f;
#pragma unroll
        for (int ks = 0; ks < 4; ks++) {
            int c = ks*16 + (lane & 3)*2;
            u32 ah0 = *reinterpret_cast<u32*>(&Qh[rq*FA_RS + c]);
            u32 ah1 = *reinterpret_cast<u32*>(&Qh[(rq+8)*FA_RS + c]);
            u32 ah2 = *reinterpret_cast<u32*>(&Qh[rq*FA_RS + c + 8]);
            u32 ah3 = *reinterpret_cast<u32*>(&Qh[(rq+8)*FA_RS + c + 8]);
            u32 al0 = *reinterpret_cast<u32*>(&Ql[rq*FA_RS + c]);
            u32 al1 = *reinterpret_cast<u32*>(&Ql[(rq+8)*FA_RS + c]);
            u32 al2 = *reinterpret_cast<u32*>(&Ql[rq*FA_RS + c + 8]);
            u32 al3 = *reinterpret_cast<u32*>(&Ql[(rq+8)*FA_RS + c + 8]);
#pragma unroll
            for (int nf = 0; nf < 8; nf++) {
                int n = nf*8 + (lane >> 2);
                u32 bh0 = *reinterpret_cast<u32*>(&Kh[n*FA_RS + c]);
                u32 bh1 = *reinterpret_cast<u32*>(&Kh[n*FA_RS + c + 8]);
                u32 bl0 = *reinterpret_cast<u32*>(&Kl[n*FA_RS + c]);
                u32 bl1 = *reinterpret_cast<u32*>(&Kl[n*FA_RS + c + 8]);
                mma_bf16(sacc[nf], ah0,ah1,ah2,ah3, bh0,bh1);
                mma_bf16(sacc[nf], ah0,ah1,ah2,ah3, bl0,bl1);
                mma_bf16(sacc[nf], al0,al1,al2,al3, bh0,bh1);
            }
        }

        // ---- online softmax ----
        float tm_lo = -1e30f, tm_hi = -1e30f;
#pragma unroll
        for (int nf = 0; nf < 8; nf++) {
            tm_lo = fmaxf(tm_lo, fmaxf(sacc[nf][0], sacc[nf][1]));
            tm_hi = fmaxf(tm_hi, fmaxf(sacc[nf][2], sacc[nf][3]));
        }
        tm_lo = fmaxf(tm_lo, __shfl_xor_sync(0xffffffffu, tm_lo, 1));
        tm_lo = fmaxf(tm_lo, __shfl_xor_sync(0xffffffffu, tm_lo, 2));
        tm_hi = fmaxf(tm_hi, __shfl_xor_sync(0xffffffffu, tm_hi, 1));
        tm_hi = fmaxf(tm_hi, __shfl_xor_sync(0xffffffffu, tm_hi, 2));
        float mn_lo = fmaxf(m_lo, tm_lo), mn_hi = fmaxf(m_hi, tm_hi);
        float f_lo = fast_exp(m_lo - mn_lo), f_hi = fast_exp(m_hi - mn_hi);
        m_lo = mn_lo; m_hi = mn_hi;

        float ts_lo = 0.f, ts_hi = 0.f;
        u32 plo[8], phi[8];
#pragma unroll
        for (int nf = 0; nf < 8; nf++) {
            float p0 = fast_exp(sacc[nf][0] - mn_lo);
            float p1 = fast_exp(sacc[nf][1] - mn_lo);
            float p2 = fast_exp(sacc[nf][2] - mn_hi);
            float p3 = fast_exp(sacc[nf][3] - mn_hi);
            ts_lo += p0 + p1; ts_hi += p2 + p3;
            __half2 hl = __floats2half2_rn(p0, p1);
            __half2 hh = __floats2half2_rn(p2, p3);
            plo[nf] = *reinterpret_cast<u32*>(&hl);
            phi[nf] = *reinterpret_cast<u32*>(&hh);
        }
        ts_lo += __shfl_xor_sync(0xffffffffu, ts_lo, 1);
        ts_lo += __shfl_xor_sync(0xffffffffu, ts_lo, 2);
        ts_hi += __shfl_xor_sync(0xffffffffu, ts_hi, 1);
        ts_hi += __shfl_xor_sync(0xffffffffu, ts_hi, 2);
        l_lo = l_lo * f_lo + ts_lo;
        l_hi = l_hi * f_hi + ts_hi;

        // rescale O
#pragma unroll
        for (int ef = 0; ef < 8; ef++) {
            o[ef][0] *= f_lo; o[ef][1] *= f_lo;
            o[ef][2] *= f_hi; o[ef][3] *= f_hi;
        }

        // ---- O += P V (fp16, 2-term split on V) ----
#pragma unroll
        for (int ks = 0; ks < 4; ks++) {
            int k0 = ks*16 + (lane & 3)*2;
            u32 a0 = plo[2*ks], a1 = phi[2*ks], a2 = plo[2*ks+1], a3 = phi[2*ks+1];
#pragma unroll
            for (int ef = 0; ef < 8; ef++) {
                int e = ef*8 + (lane >> 2);
                u32 b0h = pk(Vh[k0*FA_RS+e],     Vh[(k0+1)*FA_RS+e]);
                u32 b1h = pk(Vh[(k0+8)*FA_RS+e], Vh[(k0+9)*FA_RS+e]);
                u32 b0l = pk(Vl[k0*FA_RS+e],     Vl[(k0+1)*FA_RS+e]);
                u32 b1l = pk(Vl[(k0+8)*FA_RS+e], Vl[(k0+9)*FA_RS+e]);
                mma_f16(o[ef], a0,a1,a2,a3, b0h,b1h);
                mma_f16(o[ef], a0,a1,a2,a3, b0l,b1l);
            }
        }
    }

    // epilogue: divide by row sums, store merged layout
    float il_lo = 1.0f / l_lo, il_hi = 1.0f / l_hi;
    size_t row = (size_t)b*SEQ + q0 + rq;
#pragma unroll
    for (int ef = 0; ef < 8; ef++) {
        int col = h*HD + ef*8 + (lane & 3)*2;
        *reinterpret_cast<float2*>(&O[row*DIM + col]) =
            make_float2(o[ef][0]*il_lo, o[ef][1]*il_lo);
        *reinterpret_cast<float2*>(&O[(row+8)*DIM + col]) =
            make_float2(o[ef][2]*il_hi, o[ef][3]*il_hi);
    }
}

// ---------------- batch norm ----------------
__global__ void bn_zero()
{
    int t = blockIdx.x*256 + threadIdx.x;
    if (t < DIM) { g_sum[t] = 0.0; g_sum2[t] = 0.0; }
}

__global__ __launch_bounds__(256)
void bn_add_stats(const float* __restrict__ X, const float* __restrict__ Y,
                  float* __restrict__ Z)
{
    int f  = blockIdx.x*32 + threadIdx.x;
    int rb = blockIdx.y*512;
    float s = 0.0f, s2 = 0.0f;
    for (int r = rb + threadIdx.y; r < rb + 512; r += 8) {
        size_t idx = (size_t)r*DIM + f;
        float v = X[idx] + Y[idx];
        Z[idx] = v;
        s += v; s2 = fmaf(v, v, s2);
    }
    __shared__ double sh[2][8][32];
    sh[0][threadIdx.y][threadIdx.x] = (double)s;
    sh[1][threadIdx.y][threadIdx.x] = (double)s2;
    __syncthreads();
    if (threadIdx.y == 0) {
        double ts = 0.0, ts2 = 0.0;
#pragma unroll
        for (int i = 0; i < 8; i++) { ts += sh[0][i][threadIdx.x]; ts2 += sh[1][i][threadIdx.x]; }
        atomicAdd(&g_sum[f], ts);
        atomicAdd(&g_sum2[f], ts2);
    }
}

__global__ void bn_finalize(const float* __restrict__ g, const float* __restrict__ b)
{
    int f = blockIdx.x*256 + threadIdx.x;
    if (f >= DIM) return;
    double mu  = g_sum[f]  * (1.0 / ROWS);
    double var = g_sum2[f] * (1.0 / ROWS) - mu*mu;
    float rstd = (float)(1.0 / sqrt(var + 1e-5));
    float sc = g[f] * rstd;
    g_bnsc[f] = sc;
    g_bnsh[f] = b[f] - (float)mu * sc;
}

__global__ void bn_apply(const float* __restrict__ Z, float* __restrict__ O)
{
    int idx = blockIdx.x*256 + threadIdx.x;
    if (idx >= ROWS*DIM) return;
    int f = idx % DIM;
    O[idx] = fmaf(Z[idx], g_bnsc[f], g_bnsh[f]);
}

// ---------------- launch ----------------
static float* sym(const void* s)
{
    void* p = nullptr;
    cudaGetSymbolAddress(&p, s);
    return (float*)p;
}

extern "C" void kernel_launch(void* const* d_in, const int* in_sizes, int n_in,
                              void* d_out, int out_size)
{
    const int*   x     = (const int*)  d_in[0];
    const float* encod = (const float*)d_in[1];
    const float* embed = (const float*)d_in[2];
    const float* Wq  = (const float*)d_in[3];  const float* bq  = (const float*)d_in[4];
    const float* Wk  = (const float*)d_in[5];  const float* bk  = (const float*)d_in[6];
    const float* Wv  = (const float*)d_in[7];  const float* bv  = (const float*)d_in[8];
    const float* g1  = (const float*)d_in[9];  const float* b1  = (const float*)d_in[10];
    const float* Wq2 = (const float*)d_in[11]; const float* bq2 = (const float*)d_in[12];
    const float* Wk2 = (const float*)d_in[13]; const float* bk2 = (const float*)d_in[14];
    const float* Wv2 = (const float*)d_in[15]; const float* bv2 = (const float*)d_in[16];
    const float* Wo2 = (const float*)d_in[17]; const float* bo2 = (const float*)d_in[18];
    const float* g2  = (const float*)d_in[19]; const float* b2  = (const float*)d_in[20];
    const float* Wf  = (const float*)d_in[21]; const float* bf  = (const float*)d_in[22];
    float* out = (float*)d_out;

    float *im = sym(g_im), *q = sym(g_q), *k = sym(g_k), *v = sym(g_v);
    float *sa = sym(g_sa), *z = sym(g_z), *t1 = sym(g_t1), *v2 = sym(g_v2);
    float *av2 = sym(g_av2), *m2 = sym(g_m2), *t2 = sym(g_t2), *ff = sym(g_ff);
    float *q2 = sym(g_q2), *k2 = sym(g_k2);

    cudaFuncSetAttribute(fused_attn, cudaFuncAttributeMaxDynamicSharedMemorySize, FA_SMEM);

    const float scale1 = 1.0f / sqrtf((float)DIM);
    const float scale2 = 1.0f / sqrtf((float)HD);

    dim3 gemmGrid(DIM/128, ROWS/128);      // (6, 32)
    dim3 faGrid(SEQ/128, 1, NBH);          // (8, 1, 48)
    dim3 bnGrid(DIM/32, 8);
    dim3 bnBlk(32, 8);
    int ewBlocks = (ROWS*DIM + 255)/256;

    embed_pos_kernel<<<ewBlocks, 256>>>(x, embed, im);

    // loop-invariant cross-attention projections (probs recomputed fused per layer)
    gemm_bias_t<<<gemmGrid, 256>>>(encod, DIM, 0,   Wq2, bq2, q2, DIM, DIM/2, 0);
    gemm_bias_t<<<gemmGrid, 256>>>(encod, DIM, 384, Wk2, bk2, k2, DIM, DIM/2, 0);

    for (int li = 0; li < NITER; li++) {
        // self attention
        gemm_bias_t<<<gemmGrid, 256>>>(im, DIM, 0,   Wq, bq, q, DIM, DIM/3, 1);
        gemm_bias_t<<<gemmGrid, 256>>>(im, DIM, 256, Wk, bk, k, DIM, DIM/3, 1);
        gemm_bias_t<<<gemmGrid, 256>>>(im, DIM, 512, Wv, bv, v, DIM, DIM/3, 1);
        fused_attn<<<faGrid, 256, FA_SMEM>>>(q, k, v, sa, scale1);

        bn_zero<<<3, 256>>>();
        bn_add_stats<<<bnGrid, bnBlk>>>(im, sa, z);
        bn_finalize<<<3, 256>>>(g1, b1);
        bn_apply<<<ewBlocks, 256>>>(z, t1);

        // cross attention (flash; probs recomputed, no A2 materialization)
        gemm_bias_t<<<gemmGrid, 256>>>(t1, DIM, 0, Wv2, bv2, v2, DIM, DIM, 0);
        fused_attn<<<faGrid, 256, FA_SMEM>>>(q2, k2, v2, av2, scale2);
        gemm_bias_t<<<gemmGrid, 256>>>(av2, DIM, 0, Wo2, bo2, m2, DIM, DIM, 0);

        bn_zero<<<3, 256>>>();
        bn_add_stats<<<bnGrid, bnBlk>>>(m2, t1, z);
        bn_finalize<<<3, 256>>>(g2, b2);
        bn_apply<<<ewBlocks, 256>>>(z, t2);

        // FFN + bn3
        gemm_bias_t<<<gemmGrid, 256>>>(t2, DIM, 0, Wf, bf, ff, DIM, DIM, 0);
        bn_zero<<<3, 256>>>();
        bn_add_stats<<<bnGrid, bnBlk>>>(t2, ff, z);
        bn_finalize<<<3, 256>>>(g2, b2);
        bn_apply<<<ewBlocks, 256>>>(z, im);
    }

    cudaMemcpyAsync(out, im, (size_t)ROWS*DIM*sizeof(float),
                    cudaMemcpyDeviceToDevice);
}

// round 9
// speedup vs baseline: 3.0168x; 1.0673x over previous
#include <cuda_runtime.h>
#include <cuda_bf16.h>
#include <cuda_fp16.h>
#include <math.h>

#define BSZ   4
#define SEQ   1024
#define DIM   768
#define NH    12
#define HD    64
#define ROWS  (BSZ*SEQ)      // 4096
#define NBH   (BSZ*NH)       // 48
#define NITER 2

typedef unsigned short u16;
typedef unsigned int   u32;

// weight-split offsets (elements)
#define OFF_Q   0
#define OFF_K   196608
#define OFF_V   393216
#define OFF_Q2  589824
#define OFF_K2  884736
#define OFF_V2  1179648
#define OFF_O2  1769472
#define OFF_F   2359296
#define WSP_TOT 2949120

// ---------------- static scratch (no allocations allowed) ----------------
__device__ float g_im [ROWS*DIM];
__device__ float g_q  [ROWS*DIM];
__device__ float g_k  [ROWS*DIM];
__device__ float g_v  [ROWS*DIM];
__device__ float g_sa [ROWS*DIM];
__device__ float g_t1 [ROWS*DIM];
__device__ float g_v2 [ROWS*DIM];
__device__ float g_av2[ROWS*DIM];
__device__ float g_m2 [ROWS*DIM];
__device__ float g_t2 [ROWS*DIM];
__device__ float g_ff [ROWS*DIM];
__device__ float g_q2 [ROWS*DIM];
__device__ float g_k2 [ROWS*DIM];
__device__ u16   g_Wh [WSP_TOT];
__device__ u16   g_Wl [WSP_TOT];
__device__ double g_psum [8][DIM];
__device__ double g_psum2[8][DIM];
__device__ float  g_bnsc[DIM];
__device__ float  g_bnsh[DIM];

// ---------------- helpers ----------------
__device__ __forceinline__ void bsplit(float x, u16& h, u16& l)
{
    __nv_bfloat16 bh = __float2bfloat16(x);
    h = __bfloat16_as_ushort(bh);
    l = __bfloat16_as_ushort(__float2bfloat16(x - __bfloat162float(bh)));
}
__device__ __forceinline__ void hsplit(float x, u16& h, u16& l)
{
    __half hh = __float2half_rn(x);
    h = __half_as_ushort(hh);
    l = __half_as_ushort(__float2half_rn(x - __half2float(hh)));
}
__device__ __forceinline__ u32 pk(u16 a, u16 b) { return (u32)a | ((u32)b << 16); }

__device__ __forceinline__ void mma_bf16(float d[4], u32 a0, u32 a1, u32 a2, u32 a3,
                                         u32 b0, u32 b1)
{
    asm volatile(
        "mma.sync.aligned.m16n8k16.row.col.f32.bf16.bf16.f32 "
        "{%0,%1,%2,%3}, {%4,%5,%6,%7}, {%8,%9}, {%0,%1,%2,%3};\n"
        : "+f"(d[0]), "+f"(d[1]), "+f"(d[2]), "+f"(d[3])
        : "r"(a0), "r"(a1), "r"(a2), "r"(a3), "r"(b0), "r"(b1));
}
__device__ __forceinline__ void mma_f16(float d[4], u32 a0, u32 a1, u32 a2, u32 a3,
                                        u32 b0, u32 b1)
{
    asm volatile(
        "mma.sync.aligned.m16n8k16.row.col.f32.f16.f16.f32 "
        "{%0,%1,%2,%3}, {%4,%5,%6,%7}, {%8,%9}, {%0,%1,%2,%3};\n"
        : "+f"(d[0]), "+f"(d[1]), "+f"(d[2]), "+f"(d[3])
        : "r"(a0), "r"(a1), "r"(a2), "r"(a3), "r"(b0), "r"(b1));
}

// fast exp: pure FMA/ALU (no MUFU); x <= 0, rel err ~2e-6
__device__ __forceinline__ float fast_exp(float x)
{
    float t = fmaxf(x * 1.4426950408889634f, -120.0f);
    float r = t + 12582912.0f;
    float nf = r - 12582912.0f;
    float f = t - nf;
    float p = 1.3333558146e-3f;
    p = fmaf(p, f, 9.6181291077e-3f);
    p = fmaf(p, f, 5.5504108664e-2f);
    p = fmaf(p, f, 2.4022650695e-1f);
    p = fmaf(p, f, 6.9314718056e-1f);
    p = fmaf(p, f, 1.0f);
    int n = __float_as_int(r) - 0x4B400000;
    return __int_as_float(__float_as_int(p) + (n << 23));
}

// ---------------- weight pre-split (runs once per replay, tiny) ----------------
__global__ void wsplit_kernel(const float* __restrict__ W, int n, int off)
{
    int i = blockIdx.x*256 + threadIdx.x;
    if (i >= n) return;
    u16 h, l;
    bsplit(W[i], h, l);
    g_Wh[off + i] = h;
    g_Wl[off + i] = l;
}

// ---------------- embedding + positional encoding ----------------
__global__ void embed_pos_kernel(const int* __restrict__ x,
                                 const float* __restrict__ embed,
                                 float* __restrict__ out)
{
    int idx = blockIdx.x * 256 + threadIdx.x;
    if (idx >= ROWS*DIM) return;
    int r = idx / DIM, d = idx - r*DIM;
    int s = r & (SEQ-1);
    int tok = x[r];
    int i = d >> 1;
    float inv = exp2f((float)i * (-13.287712379549449f * 2.0f / (float)DIM));
    float ang = (float)s * inv;
    float pe = (d & 1) ? cosf(ang) : sinf(ang);
    out[idx] = 2.0f * embed[(size_t)tok * DIM + d] + pe;
}

// ---------------- shared GEMM body (A fp32 -> split; W pre-split) ----------------
#define GA_RS 40
#define GB_RS 136
__device__ __forceinline__ void gemm_body(
    const float* __restrict__ Ab, int lda,
    const u16* __restrict__ Wh, const u16* __restrict__ Wl,
    const float* __restrict__ bias, float* __restrict__ C,
    int N, int K, int bm, int bn, int relu,
    u16* Ah, u16* Al, u16* Bh, u16* Bl)
{
    int tid = threadIdx.x;
    int lane = tid & 31, wid = tid >> 5;
    int wm = wid & 1, wn = wid >> 1;

    float acc[4][4][4];
#pragma unroll
    for (int i=0;i<4;i++)
#pragma unroll
        for (int j=0;j<4;j++)
#pragma unroll
            for (int q=0;q<4;q++) acc[i][j][q]=0.f;

    for (int kb = 0; kb < K; kb += 32) {
        // A tile 128x32 fp32 -> split
#pragma unroll
        for (int it = 0; it < 4; it++) {
            int idx = it*256 + tid;
            int r = idx >> 3, c4 = (idx & 7) * 4;
            float4 v = *reinterpret_cast<const float4*>(Ab + (size_t)r*lda + kb + c4);
            u16 h0,l0,h1,l1,h2,l2,h3,l3;
            bsplit(v.x,h0,l0); bsplit(v.y,h1,l1); bsplit(v.z,h2,l2); bsplit(v.w,h3,l3);
            *reinterpret_cast<u32*>(&Ah[r*GA_RS + c4])     = pk(h0,h1);
            *reinterpret_cast<u32*>(&Ah[r*GA_RS + c4 + 2]) = pk(h2,h3);
            *reinterpret_cast<u32*>(&Al[r*GA_RS + c4])     = pk(l0,l1);
            *reinterpret_cast<u32*>(&Al[r*GA_RS + c4 + 2]) = pk(l2,l3);
        }
        // B tile 32x128 pre-split: plain uint4 copies
#pragma unroll
        for (int it = 0; it < 2; it++) {
            int idx = it*256 + tid;
            int kk = idx >> 4, c8 = (idx & 15) * 8;
            *reinterpret_cast<uint4*>(&Bh[kk*GB_RS + c8]) =
                *reinterpret_cast<const uint4*>(&Wh[(size_t)(kb+kk)*N + bn + c8]);
            *reinterpret_cast<uint4*>(&Bl[kk*GB_RS + c8]) =
                *reinterpret_cast<const uint4*>(&Wl[(size_t)(kb+kk)*N + bn + c8]);
        }
        __syncthreads();
#pragma unroll
        for (int ks = 0; ks < 32; ks += 16) {
            u32 bhf[4][2], blf[4][2];
#pragma unroll
            for (int nf = 0; nf < 4; nf++) {
                int n  = wn*32 + nf*8 + (lane >> 2);
                int k0 = ks + (lane & 3)*2;
                bhf[nf][0] = pk(Bh[k0*GB_RS+n],     Bh[(k0+1)*GB_RS+n]);
                bhf[nf][1] = pk(Bh[(k0+8)*GB_RS+n], Bh[(k0+9)*GB_RS+n]);
                blf[nf][0] = pk(Bl[k0*GB_RS+n],     Bl[(k0+1)*GB_RS+n]);
                blf[nf][1] = pk(Bl[(k0+8)*GB_RS+n], Bl[(k0+9)*GB_RS+n]);
            }
#pragma unroll
            for (int mf = 0; mf < 4; mf++) {
                int r = wm*64 + mf*16 + (lane >> 2);
                int c = ks + (lane & 3)*2;
                u32 ah0 = *reinterpret_cast<u32*>(&Ah[r*GA_RS + c]);
                u32 ah1 = *reinterpret_cast<u32*>(&Ah[(r+8)*GA_RS + c]);
                u32 ah2 = *reinterpret_cast<u32*>(&Ah[r*GA_RS + c + 8]);
                u32 ah3 = *reinterpret_cast<u32*>(&Ah[(r+8)*GA_RS + c + 8]);
                u32 al0 = *reinterpret_cast<u32*>(&Al[r*GA_RS + c]);
                u32 al1 = *reinterpret_cast<u32*>(&Al[(r+8)*GA_RS + c]);
                u32 al2 = *reinterpret_cast<u32*>(&Al[r*GA_RS + c + 8]);
                u32 al3 = *reinterpret_cast<u32*>(&Al[(r+8)*GA_RS + c + 8]);
#pragma unroll
                for (int nf = 0; nf < 4; nf++) {
                    mma_bf16(acc[mf][nf], ah0,ah1,ah2,ah3, bhf[nf][0], bhf[nf][1]);
                    mma_bf16(acc[mf][nf], ah0,ah1,ah2,ah3, blf[nf][0], blf[nf][1]);
                    mma_bf16(acc[mf][nf], al0,al1,al2,al3, bhf[nf][0], bhf[nf][1]);
                }
            }
        }
        __syncthreads();
    }
#pragma unroll
    for (int mf = 0; mf < 4; mf++) {
#pragma unroll
        for (int nf = 0; nf < 4; nf++) {
            int r = bm + wm*64 + mf*16 + (lane >> 2);
            int c = bn + wn*32 + nf*8 + (lane & 3)*2;
            float b0 = bias[c], b1 = bias[c+1];
            float v0 = acc[mf][nf][0] + b0, v1 = acc[mf][nf][1] + b1;
            float v2 = acc[mf][nf][2] + b0, v3 = acc[mf][nf][3] + b1;
            if (relu) { v0=fmaxf(v0,0.f); v1=fmaxf(v1,0.f); v2=fmaxf(v2,0.f); v3=fmaxf(v3,0.f); }
            *reinterpret_cast<float2*>(&C[(size_t)r*N + c])     = make_float2(v0, v1);
            *reinterpret_cast<float2*>(&C[(size_t)(r+8)*N + c]) = make_float2(v2, v3);
        }
    }
}

// generic GEMM launch wrapper
__global__ __launch_bounds__(256, 2)
void gemm_bias_t(const float* __restrict__ A, int lda, int aoff,
                 const u16* __restrict__ Wh, const u16* __restrict__ Wl,
                 const float* __restrict__ bias, float* __restrict__ C,
                 int N, int K, int relu)
{
    __shared__ __align__(16) u16 Ah[128*GA_RS], Al[128*GA_RS];
    __shared__ __align__(16) u16 Bh[32*GB_RS],  Bl[32*GB_RS];
    int bm = blockIdx.y*128, bn = blockIdx.x*128;
    gemm_body(A + (size_t)bm*lda + aoff, lda, Wh, Wl, bias, C,
              N, K, bm, bn, relu, Ah, Al, Bh, Bl);
}

// fused QKV: grid (18, 32); group = x/6 selects q/k/v
__global__ __launch_bounds__(256, 2)
void qkv_gemm_t(const float* __restrict__ A,
                const float* __restrict__ bq, const float* __restrict__ bk,
                const float* __restrict__ bv)
{
    __shared__ __align__(16) u16 Ah[128*GA_RS], Al[128*GA_RS];
    __shared__ __align__(16) u16 Bh[32*GB_RS],  Bl[32*GB_RS];
    int grp = blockIdx.x / 6;
    int bxl = blockIdx.x - grp*6;
    int bm = blockIdx.y*128, bn = bxl*128;
    const u16* Wh = g_Wh + grp*196608;
    const u16* Wl = g_Wl + grp*196608;
    const float* bias = (grp == 0) ? bq : (grp == 1) ? bk : bv;
    float* C = (grp == 0) ? g_q : (grp == 1) ? g_k : g_v;
    int aoff = grp*256;
    gemm_body(A + (size_t)bm*DIM + aoff, DIM, Wh, Wl, bias, C,
              DIM, 256, bm, bn, 1, Ah, Al, Bh, Bl);
}

// ---------------- fused flash attention: O = softmax(scale*Q K^T) V ----------------
#define FA_RS 72
#define FA_SMEM ((2*128*FA_RS + 4*64*FA_RS) * 2)   // 73728 bytes
__global__ __launch_bounds__(256, 2)
void fused_attn(const float* __restrict__ Q, const float* __restrict__ K_,
                const float* __restrict__ V_, float* __restrict__ O, float scale)
{
    extern __shared__ u16 sm[];
    u16* Qh = sm;
    u16* Ql = Qh + 128*FA_RS;
    u16* Kh = Ql + 128*FA_RS;
    u16* Kl = Kh + 64*FA_RS;
    u16* Vh = Kl + 64*FA_RS;
    u16* Vl = Vh + 64*FA_RS;

    int bh = blockIdx.z;
    int b = bh / NH, h = bh - b*NH;
    int tid = threadIdx.x, lane = tid & 31, w = tid >> 5;
    size_t base = ((size_t)b*SEQ)*DIM + h*HD;
    int q0 = blockIdx.x * 128;

#pragma unroll
    for (int it = 0; it < 8; it++) {
        int idx = it*256 + tid;
        int r = idx >> 4, c4 = (idx & 15) * 4;
        float4 v = *reinterpret_cast<const float4*>(&Q[base + (size_t)(q0+r)*DIM + c4]);
        v.x *= scale; v.y *= scale; v.z *= scale; v.w *= scale;
        u16 h0,l0,h1,l1,h2,l2,h3,l3;
        bsplit(v.x,h0,l0); bsplit(v.y,h1,l1); bsplit(v.z,h2,l2); bsplit(v.w,h3,l3);
        *reinterpret_cast<u32*>(&Qh[r*FA_RS + c4])     = pk(h0,h1);
        *reinterpret_cast<u32*>(&Qh[r*FA_RS + c4 + 2]) = pk(h2,h3);
        *reinterpret_cast<u32*>(&Ql[r*FA_RS + c4])     = pk(l0,l1);
        *reinterpret_cast<u32*>(&Ql[r*FA_RS + c4 + 2]) = pk(l2,l3);
    }

    float o[8][4];
#pragma unroll
    for (int i=0;i<8;i++)
#pragma unroll
        for (int j=0;j<4;j++) o[i][j]=0.f;
    float m_lo = -1e30f, m_hi = -1e30f, l_lo = 0.f, l_hi = 0.f;

    int rq = w*16 + (lane >> 2);

    for (int t0 = 0; t0 < SEQ; t0 += 64) {
        __syncthreads();
#pragma unroll
        for (int it = 0; it < 4; it++) {
            int idx = it*256 + tid;
            int r = idx >> 4, c4 = (idx & 15) * 4;
            float4 kv = *reinterpret_cast<const float4*>(&K_[base + (size_t)(t0+r)*DIM + c4]);
            u16 h0,l0,h1,l1,h2,l2,h3,l3;
            bsplit(kv.x,h0,l0); bsplit(kv.y,h1,l1); bsplit(kv.z,h2,l2); bsplit(kv.w,h3,l3);
            *reinterpret_cast<u32*>(&Kh[r*FA_RS + c4])     = pk(h0,h1);
            *reinterpret_cast<u32*>(&Kh[r*FA_RS + c4 + 2]) = pk(h2,h3);
            *reinterpret_cast<u32*>(&Kl[r*FA_RS + c4])     = pk(l0,l1);
            *reinterpret_cast<u32*>(&Kl[r*FA_RS + c4 + 2]) = pk(l2,l3);
            float4 vv = *reinterpret_cast<const float4*>(&V_[base + (size_t)(t0+r)*DIM + c4]);
            hsplit(vv.x,h0,l0); hsplit(vv.y,h1,l1); hsplit(vv.z,h2,l2); hsplit(vv.w,h3,l3);
            *reinterpret_cast<u32*>(&Vh[r*FA_RS + c4])     = pk(h0,h1);
            *reinterpret_cast<u32*>(&Vh[r*FA_RS + c4 + 2]) = pk(h2,h3);
            *reinterpret_cast<u32*>(&Vl[r*FA_RS + c4])     = pk(l0,l1);
            *reinterpret_cast<u32*>(&Vl[r*FA_RS + c4 + 2]) = pk(l2,l3);
        }
        __syncthreads();

        float sacc[8][4];
#pragma unroll
        for (int i=0;i<8;i++)
#pragma unroll
            for (int j=0;j<4;j++) sacc[i][j]=0.f;
#pragma unroll
        for (int ks = 0; ks < 4; ks++) {
            int c = ks*16 + (lane & 3)*2;
            u32 ah0 = *reinterpret_cast<u32*>(&Qh[rq*FA_RS + c]);
            u32 ah1 = *reinterpret_cast<u32*>(&Qh[(rq+8)*FA_RS + c]);
            u32 ah2 = *reinterpret_cast<u32*>(&Qh[rq*FA_RS + c + 8]);
            u32 ah3 = *reinterpret_cast<u32*>(&Qh[(rq+8)*FA_RS + c + 8]);
            u32 al0 = *reinterpret_cast<u32*>(&Ql[rq*FA_RS + c]);
            u32 al1 = *reinterpret_cast<u32*>(&Ql[(rq+8)*FA_RS + c]);
            u32 al2 = *reinterpret_cast<u32*>(&Ql[rq*FA_RS + c + 8]);
            u32 al3 = *reinterpret_cast<u32*>(&Ql[(rq+8)*FA_RS + c + 8]);
#pragma unroll
            for (int nf = 0; nf < 8; nf++) {
                int n = nf*8 + (lane >> 2);
                u32 bh0 = *reinterpret_cast<u32*>(&Kh[n*FA_RS + c]);
                u32 bh1 = *reinterpret_cast<u32*>(&Kh[n*FA_RS + c + 8]);
                u32 bl0 = *reinterpret_cast<u32*>(&Kl[n*FA_RS + c]);
                u32 bl1 = *reinterpret_cast<u32*>(&Kl[n*FA_RS + c + 8]);
                mma_bf16(sacc[nf], ah0,ah1,ah2,ah3, bh0,bh1);
                mma_bf16(sacc[nf], ah0,ah1,ah2,ah3, bl0,bl1);
                mma_bf16(sacc[nf], al0,al1,al2,al3, bh0,bh1);
            }
        }

        float tm_lo = -1e30f, tm_hi = -1e30f;
#pragma unroll
        for (int nf = 0; nf < 8; nf++) {
            tm_lo = fmaxf(tm_lo, fmaxf(sacc[nf][0], sacc[nf][1]));
            tm_hi = fmaxf(tm_hi, fmaxf(sacc[nf][2], sacc[nf][3]));
        }
        tm_lo = fmaxf(tm_lo, __shfl_xor_sync(0xffffffffu, tm_lo, 1));
        tm_lo = fmaxf(tm_lo, __shfl_xor_sync(0xffffffffu, tm_lo, 2));
        tm_hi = fmaxf(tm_hi, __shfl_xor_sync(0xffffffffu, tm_hi, 1));
        tm_hi = fmaxf(tm_hi, __shfl_xor_sync(0xffffffffu, tm_hi, 2));
        float mn_lo = fmaxf(m_lo, tm_lo), mn_hi = fmaxf(m_hi, tm_hi);
        float f_lo = fast_exp(m_lo - mn_lo), f_hi = fast_exp(m_hi - mn_hi);
        m_lo = mn_lo; m_hi = mn_hi;

        float ts_lo = 0.f, ts_hi = 0.f;
        u32 plo[8], phi[8];
#pragma unroll
        for (int nf = 0; nf < 8; nf++) {
            float p0 = fast_exp(sacc[nf][0] - mn_lo);
            float p1 = fast_exp(sacc[nf][1] - mn_lo);
            float p2 = fast_exp(sacc[nf][2] - mn_hi);
            float p3 = fast_exp(sacc[nf][3] - mn_hi);
            ts_lo += p0 + p1; ts_hi += p2 + p3;
            __half2 hl = __floats2half2_rn(p0, p1);
            __half2 hh = __floats2half2_rn(p2, p3);
            plo[nf] = *reinterpret_cast<u32*>(&hl);
            phi[nf] = *reinterpret_cast<u32*>(&hh);
        }
        ts_lo += __shfl_xor_sync(0xffffffffu, ts_lo, 1);
        ts_lo += __shfl_xor_sync(0xffffffffu, ts_lo, 2);
        ts_hi += __shfl_xor_sync(0xffffffffu, ts_hi, 1);
        ts_hi += __shfl_xor_sync(0xffffffffu, ts_hi, 2);
        l_lo = l_lo * f_lo + ts_lo;
        l_hi = l_hi * f_hi + ts_hi;

#pragma unroll
        for (int ef = 0; ef < 8; ef++) {
            o[ef][0] *= f_lo; o[ef][1] *= f_lo;
            o[ef][2] *= f_hi; o[ef][3] *= f_hi;
        }

#pragma unroll
        for (int ks = 0; ks < 4; ks++) {
            int k0 = ks*16 + (lane & 3)*2;
            u32 a0 = plo[2*ks], a1 = phi[2*ks], a2 = plo[2*ks+1], a3 = phi[2*ks+1];
#pragma unroll
            for (int ef = 0; ef < 8; ef++) {
                int e = ef*8 + (lane >> 2);
                u32 b0h = pk(Vh[k0*FA_RS+e],     Vh[(k0+1)*FA_RS+e]);
                u32 b1h = pk(Vh[(k0+8)*FA_RS+e], Vh[(k0+9)*FA_RS+e]);
                u32 b0l = pk(Vl[k0*FA_RS+e],     Vl[(k0+1)*FA_RS+e]);
                u32 b1l = pk(Vl[(k0+8)*FA_RS+e], Vl[(k0+9)*FA_RS+e]);
                mma_f16(o[ef], a0,a1,a2,a3, b0h,b1h);
                mma_f16(o[ef], a0,a1,a2,a3, b0l,b1l);
            }
        }
    }

    float il_lo = 1.0f / l_lo, il_hi = 1.0f / l_hi;
    size_t row = (size_t)b*SEQ + q0 + rq;
#pragma unroll
    for (int ef = 0; ef < 8; ef++) {
        int col = h*HD + ef*8 + (lane & 3)*2;
        *reinterpret_cast<float2*>(&O[row*DIM + col]) =
            make_float2(o[ef][0]*il_lo, o[ef][1]*il_lo);
        *reinterpret_cast<float2*>(&O[(row+8)*DIM + col]) =
            make_float2(o[ef][2]*il_hi, o[ef][3]*il_hi);
    }
}

// ---------------- batch norm (partial sums, no atomics, no Z buffer) ----------------
__global__ __launch_bounds__(256)
void bn_stats(const float* __restrict__ X, const float* __restrict__ Y)
{
    int f  = blockIdx.x*32 + threadIdx.x;
    int rb = blockIdx.y*512;
    float s = 0.0f, s2 = 0.0f;
    for (int r = rb + threadIdx.y; r < rb + 512; r += 8) {
        size_t idx = (size_t)r*DIM + f;
        float v = X[idx] + Y[idx];
        s += v; s2 = fmaf(v, v, s2);
    }
    __shared__ double sh[2][8][32];
    sh[0][threadIdx.y][threadIdx.x] = (double)s;
    sh[1][threadIdx.y][threadIdx.x] = (double)s2;
    __syncthreads();
    if (threadIdx.y == 0) {
        double ts = 0.0, ts2 = 0.0;
#pragma unroll
        for (int i = 0; i < 8; i++) { ts += sh[0][i][threadIdx.x]; ts2 += sh[1][i][threadIdx.x]; }
        g_psum [blockIdx.y][f] = ts;
        g_psum2[blockIdx.y][f] = ts2;
    }
}

__global__ void bn_finalize(const float* __restrict__ g, const float* __restrict__ b)
{
    int f = blockIdx.x*256 + threadIdx.x;
    if (f >= DIM) return;
    double s = 0.0, s2 = 0.0;
#pragma unroll
    for (int i = 0; i < 8; i++) { s += g_psum[i][f]; s2 += g_psum2[i][f]; }
    double mu  = s  * (1.0 / ROWS);
    double var = s2 * (1.0 / ROWS) - mu*mu;
    float rstd = (float)(1.0 / sqrt(var + 1e-5));
    float sc = g[f] * rstd;
    g_bnsc[f] = sc;
    g_bnsh[f] = b[f] - (float)mu * sc;
}

// O = ((X+Y) - mu) * sc + sh, vectorized
__global__ __launch_bounds__(256)
void bn_apply2(const float* __restrict__ X, const float* __restrict__ Y,
               float* __restrict__ O)
{
    int idx4 = blockIdx.x*256 + threadIdx.x;
    if (idx4 >= ROWS*DIM/4) return;
    int f = (idx4*4) % DIM;
    float4 x = *reinterpret_cast<const float4*>(&X[(size_t)idx4*4]);
    float4 y = *reinterpret_cast<const float4*>(&Y[(size_t)idx4*4]);
    float4 o;
    o.x = fmaf(x.x + y.x, g_bnsc[f+0], g_bnsh[f+0]);
    o.y = fmaf(x.y + y.y, g_bnsc[f+1], g_bnsh[f+1]);
    o.z = fmaf(x.z + y.z, g_bnsc[f+2], g_bnsh[f+2]);
    o.w = fmaf(x.w + y.w, g_bnsc[f+3], g_bnsh[f+3]);
    *reinterpret_cast<float4*>(&O[(size_t)idx4*4]) = o;
}

// ---------------- launch ----------------
static float* sym(const void* s)
{
    void* p = nullptr;
    cudaGetSymbolAddress(&p, s);
    return (float*)p;
}

extern "C" void kernel_launch(void* const* d_in, const int* in_sizes, int n_in,
                              void* d_out, int out_size)
{
    const int*   x     = (const int*)  d_in[0];
    const float* encod = (const float*)d_in[1];
    const float* embed = (const float*)d_in[2];
    const float* Wq  = (const float*)d_in[3];  const float* bq  = (const float*)d_in[4];
    const float* Wk  = (const float*)d_in[5];  const float* bk  = (const float*)d_in[6];
    const float* Wv  = (const float*)d_in[7];  const float* bv  = (const float*)d_in[8];
    const float* g1  = (const float*)d_in[9];  const float* b1  = (const float*)d_in[10];
    const float* Wq2 = (const float*)d_in[11]; const float* bq2 = (const float*)d_in[12];
    const float* Wk2 = (const float*)d_in[13]; const float* bk2 = (const float*)d_in[14];
    const float* Wv2 = (const float*)d_in[15]; const float* bv2 = (const float*)d_in[16];
    const float* Wo2 = (const float*)d_in[17]; const float* bo2 = (const float*)d_in[18];
    const float* g2  = (const float*)d_in[19]; const float* b2  = (const float*)d_in[20];
    const float* Wf  = (const float*)d_in[21]; const float* bf  = (const float*)d_in[22];
    float* out = (float*)d_out;

    float *im = sym(g_im), *q = sym(g_q), *k = sym(g_k), *v = sym(g_v);
    float *sa = sym(g_sa), *t1 = sym(g_t1), *v2 = sym(g_v2);
    float *av2 = sym(g_av2), *m2 = sym(g_m2), *t2 = sym(g_t2), *ff = sym(g_ff);
    float *q2 = sym(g_q2), *k2 = sym(g_k2);
    u16 *wh = (u16*)sym(g_Wh), *wl = (u16*)sym(g_Wl);

    cudaFuncSetAttribute(fused_attn, cudaFuncAttributeMaxDynamicSharedMemorySize, FA_SMEM);

    const float scale1 = 1.0f / sqrtf((float)DIM);
    const float scale2 = 1.0f / sqrtf((float)HD);

    dim3 gemmGrid(DIM/128, ROWS/128);      // (6, 32)
    dim3 qkvGrid(3*DIM/128, ROWS/128);     // (18, 32)
    dim3 faGrid(SEQ/128, 1, NBH);          // (8, 1, 48)
    dim3 bnGrid(DIM/32, 8);
    dim3 bnBlk(32, 8);
    int ewBlocks = (ROWS*DIM + 255)/256;
    int ew4Blocks = (ROWS*DIM/4 + 255)/256;

    // weight pre-split (once per replay)
    wsplit_kernel<<<(196608+255)/256, 256>>>(Wq,  196608, OFF_Q);
    wsplit_kernel<<<(196608+255)/256, 256>>>(Wk,  196608, OFF_K);
    wsplit_kernel<<<(196608+255)/256, 256>>>(Wv,  196608, OFF_V);
    wsplit_kernel<<<(294912+255)/256, 256>>>(Wq2, 294912, OFF_Q2);
    wsplit_kernel<<<(294912+255)/256, 256>>>(Wk2, 294912, OFF_K2);
    wsplit_kernel<<<(589824+255)/256, 256>>>(Wv2, 589824, OFF_V2);
    wsplit_kernel<<<(589824+255)/256, 256>>>(Wo2, 589824, OFF_O2);
    wsplit_kernel<<<(589824+255)/256, 256>>>(Wf,  589824, OFF_F);

    embed_pos_kernel<<<ewBlocks, 256>>>(x, embed, im);

    // loop-invariant cross-attention projections
    gemm_bias_t<<<gemmGrid, 256>>>(encod, DIM, 0,   wh+OFF_Q2, wl+OFF_Q2, bq2, q2, DIM, DIM/2, 0);
    gemm_bias_t<<<gemmGrid, 256>>>(encod, DIM, 384, wh+OFF_K2, wl+OFF_K2, bk2, k2, DIM, DIM/2, 0);

    for (int li = 0; li < NITER; li++) {
        // self attention
        qkv_gemm_t<<<qkvGrid, 256>>>(im, bq, bk, bv);
        fused_attn<<<faGrid, 256, FA_SMEM>>>(q, k, v, sa, scale1);

        bn_stats<<<bnGrid, bnBlk>>>(im, sa);
        bn_finalize<<<3, 256>>>(g1, b1);
        bn_apply2<<<ew4Blocks, 256>>>(im, sa, t1);

        // cross attention (flash; probs recomputed)
        gemm_bias_t<<<gemmGrid, 256>>>(t1, DIM, 0, wh+OFF_V2, wl+OFF_V2, bv2, v2, DIM, DIM, 0);
        fused_attn<<<faGrid, 256, FA_SMEM>>>(q2, k2, v2, av2, scale2);
        gemm_bias_t<<<gemmGrid, 256>>>(av2, DIM, 0, wh+OFF_O2, wl+OFF_O2, bo2, m2, DIM, DIM, 0);

        bn_stats<<<bnGrid, bnBlk>>>(m2, t1);
        bn_finalize<<<3, 256>>>(g2, b2);
        bn_apply2<<<ew4Blocks, 256>>>(m2, t1, t2);

        // FFN + bn3
        gemm_bias_t<<<gemmGrid, 256>>>(t2, DIM, 0, wh+OFF_F, wl+OFF_F, bf, ff, DIM, DIM, 0);
        bn_stats<<<bnGrid, bnBlk>>>(t2, ff);
        bn_finalize<<<3, 256>>>(g2, b2);
        bn_apply2<<<ew4Blocks, 256>>>(t2, ff, im);
    }

    cudaMemcpyAsync(out, im, (size_t)ROWS*DIM*sizeof(float),
                    cudaMemcpyDeviceToDevice);
}